// round 12
// baseline (speedup 1.0000x reference)
#include <cuda_runtime.h>
#include <cuda_fp16.h>
#include <cstdint>

#define NN   50000
#define EE   600000
#define DD   128
#define DOUT 64
#define NB   ((NN + 255) / 256)   // 196

// PDL: wait for the grid we depend on before touching its data.
#define PDL_WAIT() asm volatile("griddepcontrol.wait;" ::: "memory")

// ---------------- scratch ----------------
__device__ __half g_hA[(size_t)NN * DD];
__device__ __half g_hB[(size_t)NN * DD];
__device__ __half g_w1h[DD * DD], g_w1l[DD * DD];      // W1^T fp16 split
__device__ __half g_w2h[DD * DD], g_w2l[DD * DD];      // (W2^2)^T fp16 split
__device__ __half g_woh[DOUT * DD], g_wol[DOUT * DD];  // Wout^T fp16 split
__device__ float g_bw1[DD], g_bw2[DD];                 // b1@W1, b2@W2
__device__ float g_degf[NN], g_adeg[NN];
__device__ int g_deg[NN], g_cnt[NN], g_off[NN + 1];
__device__ int g_csr[EE];
__device__ int g_is64;

__device__ __forceinline__ uint32_t smem_u32(const void* p) {
    uint32_t a;
    asm("{ .reg .u64 t; cvta.to.shared.u64 t, %1; cvt.u32.u64 %0, t; }" : "=r"(a) : "l"(p));
    return a;
}

__device__ __forceinline__ int edge_idx(const void* ei, int which, int e) {
    if (g_is64) return (int)((const long long*)ei)[(size_t)which * EE + e];
    return ((const int*)ei)[which * EE + e];
}

// ---------------- CSR build (side stream) ----------------
__global__ void zero_detect_kernel(const unsigned int* __restrict__ w) {
    int i = blockIdx.x * blockDim.x + threadIdx.x;
    if (i < NN) { g_deg[i] = 0; g_cnt[i] = 0; }
    if (i == 0) {
        int is64 = 1;
        for (int j = 1; j < 128; j += 2)
            if (w[j] != 0u) { is64 = 0; break; }
        g_is64 = is64;
    }
}
__global__ void hist_kernel(const void* ei) {
    PDL_WAIT();
    int e = blockIdx.x * blockDim.x + threadIdx.x;
    if (e < EE) atomicAdd(&g_deg[edge_idx(ei, 1, e)], 1);
}
// offsets: each block sums its predecessor degrees directly (no partial kernel)
__global__ void offs_kernel() {
    __shared__ int sh[256];
    __shared__ int base_sh;
    int t = threadIdx.x, bid = blockIdx.x, i = bid * 256 + t;
    PDL_WAIT();
    // sum of all degrees before this block
    int s = 0;
    for (int j = t; j < bid * 256; j += 256) s += g_deg[j];
    sh[t] = s;
    __syncthreads();
    for (int d = 128; d > 0; d >>= 1) {
        if (t < d) sh[t] += sh[t + d];
        __syncthreads();
    }
    if (t == 0) base_sh = sh[0];
    __syncthreads();
    // block-local inclusive scan
    int v = (i < NN) ? g_deg[i] : 0;
    sh[t] = v;
    __syncthreads();
    for (int d = 1; d < 256; d <<= 1) {
        int u = (t >= d) ? sh[t - d] : 0;
        __syncthreads();
        sh[t] += u;
        __syncthreads();
    }
    if (i < NN) g_off[i] = base_sh + sh[t] - v;
    if (bid == gridDim.x - 1 && t == 255) g_off[NN] = EE;
}
__global__ void fill_kernel(const void* ei) {
    PDL_WAIT();
    int e = blockIdx.x * blockDim.x + threadIdx.x;
    if (e < EE) {
        int d = edge_idx(ei, 1, e);
        int s = edge_idx(ei, 0, e);
        g_csr[g_off[d] + atomicAdd(&g_cnt[d], 1)] = s;
    }
}
__global__ void adeg_kernel() {
    PDL_WAIT();
    int i = blockIdx.x * blockDim.x + threadIdx.x;
    if (i >= NN) return;
    int b = g_off[i], e = g_off[i + 1];
    float s = 0.f;
    for (int k = b; k < e; k++) s += (float)g_deg[g_csr[k]];
    g_adeg[i] = s;
    g_degf[i] = (float)(e - b);
}

// ---------------- fp16 split helper ----------------
__device__ __forceinline__ void split2h(float x, __half& h, __half& l) {
    h = __float2half(x);
    l = __float2half(x - __half2float(h));
}

// ---------------- prep: W1^T, (W2^2)^T, Wout^T fp16 splits + bW vectors ----------------
__global__ void prep_all_kernel(const float* __restrict__ W1, const float* __restrict__ W2,
                                const float* __restrict__ Wo, const float* __restrict__ b1,
                                const float* __restrict__ b2) {
    int i = blockIdx.x * blockDim.x + threadIdx.x;
    if (i < 16384) {
        int n = i >> 7, k = i & 127;
        split2h(W1[k * DD + n], g_w1h[i], g_w1l[i]);
    } else if (i < 32768) {
        int j = i - 16384;
        int n = j >> 7, k = j & 127;
        float s = 0.f;
        for (int t = 0; t < DD; t++) s += W2[k * DD + t] * W2[t * DD + n];
        split2h(s, g_w2h[j], g_w2l[j]);
    } else if (i < 32768 + DOUT * DD) {
        int j = i - 32768;
        int n = j >> 7, k = j & 127;
        split2h(Wo[k * DOUT + n], g_woh[j], g_wol[j]);
    } else if (i < 32768 + DOUT * DD + 2 * DD) {
        int c = i - (32768 + DOUT * DD);
        if (c < DD) {
            float s = 0.f;
            for (int k = 0; k < DD; k++) s += b1[k] * W1[k * DD + c];
            g_bw1[c] = s;
        } else {
            c -= DD;
            float s = 0.f;
            for (int k = 0; k < DD; k++) s += b2[k] * W2[k * DD + c];
            g_bw2[c] = s;
        }
    }
}

// ---------------- fp16 MMA core ----------------
template <int N>
__device__ __forceinline__ void mma_pass(uint32_t sb, uint32_t aoff, uint32_t boff,
                                         float (&acc)[N / 8][4], int wid, int lane) {
    constexpr int NW = N / 2, NF16 = NW / 16, NF8 = NW / 8;
    int wr = wid & 3, wc = wid >> 2, lr = lane & 7;
    int a_half = (lane >> 3) & 1, a_kc = lane >> 4;
    int b_kc = (lane >> 3) & 1, b_nh = lane >> 4;
#pragma unroll
    for (int ks = 0; ks < 8; ks++) {
        int c0 = ks * 2;
        uint32_t a[2][4];
#pragma unroll
        for (int mf = 0; mf < 2; mf++) {
            uint32_t addr = sb + aoff + (uint32_t)((wr * 32 + mf * 16 + a_half * 8 + lr) * 256)
                          + (uint32_t)(((c0 + a_kc) ^ lr) << 4);
            asm volatile("ldmatrix.sync.aligned.m8n8.x4.shared.b16 {%0,%1,%2,%3}, [%4];"
                : "=r"(a[mf][0]), "=r"(a[mf][1]), "=r"(a[mf][2]), "=r"(a[mf][3]) : "r"(addr));
        }
#pragma unroll
        for (int nf = 0; nf < NF16; nf++) {
            uint32_t addr = sb + boff + (uint32_t)((wc * NW + nf * 16 + b_nh * 8 + lr) * 256)
                          + (uint32_t)(((c0 + b_kc) ^ lr) << 4);
            uint32_t b0, b1r, b2r, b3;
            asm volatile("ldmatrix.sync.aligned.m8n8.x4.shared.b16 {%0,%1,%2,%3}, [%4];"
                : "=r"(b0), "=r"(b1r), "=r"(b2r), "=r"(b3) : "r"(addr));
#pragma unroll
            for (int mf = 0; mf < 2; mf++) {
                float* c = acc[mf * NF8 + 2 * nf];
                asm volatile("mma.sync.aligned.m16n8k16.row.col.f32.f16.f16.f32 "
                    "{%0,%1,%2,%3}, {%4,%5,%6,%7}, {%8,%9}, {%0,%1,%2,%3};"
                    : "+f"(c[0]), "+f"(c[1]), "+f"(c[2]), "+f"(c[3])
                    : "r"(a[mf][0]), "r"(a[mf][1]), "r"(a[mf][2]), "r"(a[mf][3]), "r"(b0), "r"(b1r));
                float* d = acc[mf * NF8 + 2 * nf + 1];
                asm volatile("mma.sync.aligned.m16n8k16.row.col.f32.f16.f16.f32 "
                    "{%0,%1,%2,%3}, {%4,%5,%6,%7}, {%8,%9}, {%0,%1,%2,%3};"
                    : "+f"(d[0]), "+f"(d[1]), "+f"(d[2]), "+f"(d[3])
                    : "r"(a[mf][0]), "r"(a[mf][1]), "r"(a[mf][2]), "r"(a[mf][3]), "r"(b2r), "r"(b3));
            }
        }
    }
}

template <int N>
__device__ __forceinline__ void stageB_at(char* smem, uint32_t boff,
                                          const __half* __restrict__ B, int tid) {
    for (int idx = tid; idx < N * 16; idx += 256) {
        int r = idx >> 4, ch = idx & 15;
        uint4 v = *(const uint4*)(B + r * DD + ch * 8);
        *(uint4*)(smem + boff + r * 256 + ((ch ^ (r & 7)) << 4)) = v;
    }
}

template <int N, int EPI, int OUTF>
__device__ __forceinline__ void epilogue(float (&acc)[N / 8][4],
                                         const float* __restrict__ bias,
                                         const float* __restrict__ bw,
                                         void* __restrict__ Cv, int row0,
                                         int wid, int lane) {
    constexpr int NW = N / 2, NF8 = NW / 8;
    int wr = wid & 3, wc = wid >> 2;
    int g = lane >> 2, tg = lane & 3;
#pragma unroll
    for (int mf = 0; mf < 2; mf++) {
        int r = row0 + wr * 32 + mf * 16 + g;
        float d0 = 0.f, a0 = 0.f, d1 = 0.f, a1 = 0.f;
        if (EPI == 1) {
            if (r < NN)     { d0 = g_degf[r];     a0 = g_adeg[r]; }
            if (r + 8 < NN) { d1 = g_degf[r + 8]; a1 = g_adeg[r + 8]; }
        }
#pragma unroll
        for (int n8 = 0; n8 < NF8; n8++) {
            int c = wc * NW + n8 * 8 + tg * 2;
            float* v = acc[mf * NF8 + n8];
            float o0x = v[0], o0y = v[1], o1x = v[2], o1y = v[3];
            if (EPI == 1) {
                float bwx = bw[c], bwy = bw[c + 1], bx = bias[c], by = bias[c + 1];
                o0x = fmaxf(o0x + a0 * bwx + d0 * bx, 0.f);
                o0y = fmaxf(o0y + a0 * bwy + d0 * by, 0.f);
                o1x = fmaxf(o1x + a1 * bwx + d1 * bx, 0.f);
                o1y = fmaxf(o1y + a1 * bwy + d1 * by, 0.f);
            } else if (EPI == 2) {
                float bx = bias[c], by = bias[c + 1];
                o0x += bx; o0y += by; o1x += bx; o1y += by;
            }
            if (OUTF) {
                float* C = (float*)Cv;
                if (r < NN)
                    *(float2*)(C + (size_t)r * N + c) = make_float2(o0x, o0y);
                if (r + 8 < NN)
                    *(float2*)(C + (size_t)(r + 8) * N + c) = make_float2(o1x, o1y);
            } else {
                __half* C = (__half*)Cv;
                if (r < NN)
                    *(__half2*)(C + (size_t)r * N + c) = __floats2half2_rn(o0x, o0y);
                if (r + 8 < NN)
                    *(__half2*)(C + (size_t)(r + 8) * N + c) = __floats2half2_rn(o1x, o1y);
            }
        }
    }
}

// ---------------- on-path GEMM: A fp16 native, B fp16 hi+lo (2 passes) ----------------
template <int N, int EPI, int OUTF>
__global__ void __launch_bounds__(256, 2) gemm_on(
    const __half* __restrict__ A,
    const __half* __restrict__ Bhi, const __half* __restrict__ Blo,
    const float* __restrict__ bias, const float* __restrict__ bw,
    void* __restrict__ Cv)
{
    extern __shared__ char smem[];
    uint32_t sb = smem_u32(smem);
    int tid = threadIdx.x, wid = tid >> 5, lane = tid & 31;
    int row0 = blockIdx.x * 128;
    PDL_WAIT();

    for (int idx = tid; idx < 2048; idx += 256) {
        int r = idx >> 4, ch = idx & 15, grow = row0 + r;
        uint4 v = make_uint4(0, 0, 0, 0);
        if (grow < NN) v = *(const uint4*)(A + (size_t)grow * DD + ch * 8);
        *(uint4*)(smem + r * 256 + ((ch ^ (r & 7)) << 4)) = v;
    }
    stageB_at<N>(smem, 32768u, Bhi, tid);
    stageB_at<N>(smem, 32768u + N * 256, Blo, tid);
    __syncthreads();

    float acc[N / 8][4];
#pragma unroll
    for (int i = 0; i < N / 8; i++)
#pragma unroll
        for (int j = 0; j < 4; j++) acc[i][j] = 0.f;

    mma_pass<N>(sb, 0u, 32768u, acc, wid, lane);
    mma_pass<N>(sb, 0u, 32768u + N * 256, acc, wid, lane);

    epilogue<N, EPI, OUTF>(acc, bias, bw, Cv, row0, wid, lane);
}

// ---------------- head GEMM: fp32 X, fp16-split A (3 passes) ----------------
__global__ void __launch_bounds__(256, 2) gemm_x(
    const float* __restrict__ X,
    const __half* __restrict__ Bhi, const __half* __restrict__ Blo,
    void* __restrict__ Cv)
{
    extern __shared__ char smem[];
    constexpr int N = 128;
    uint32_t sb = smem_u32(smem);
    int tid = threadIdx.x, wid = tid >> 5, lane = tid & 31;
    int row0 = blockIdx.x * 128;
    PDL_WAIT();

    for (int idx = tid; idx < 2048; idx += 256) {
        int r = idx >> 4, ch = idx & 15, grow = row0 + r;
        __half h[8], l[8];
        if (grow < NN) {
            const float* p = X + (size_t)grow * DD + ch * 8;
            float4 v0 = *(const float4*)p, v1 = *(const float4*)(p + 4);
            float f[8] = {v0.x, v0.y, v0.z, v0.w, v1.x, v1.y, v1.z, v1.w};
#pragma unroll
            for (int j = 0; j < 8; j++) split2h(f[j], h[j], l[j]);
        } else {
#pragma unroll
            for (int j = 0; j < 8; j++) { h[j] = __float2half(0.f); l[j] = h[j]; }
        }
        int off = r * 256 + ((ch ^ (r & 7)) << 4);
        *(uint4*)(smem + off) = *(uint4*)h;
        *(uint4*)(smem + 32768 + off) = *(uint4*)l;
    }
    stageB_at<N>(smem, 65536u, Bhi, tid);
    __syncthreads();

    float acc[N / 8][4];
#pragma unroll
    for (int i = 0; i < N / 8; i++)
#pragma unroll
        for (int j = 0; j < 4; j++) acc[i][j] = 0.f;

    mma_pass<N>(sb, 0u, 65536u, acc, wid, lane);
    mma_pass<N>(sb, 32768u, 65536u, acc, wid, lane);
    __syncthreads();
    stageB_at<N>(smem, 65536u, Blo, tid);
    __syncthreads();
    mma_pass<N>(sb, 0u, 65536u, acc, wid, lane);

    epilogue<N, 0, 0>(acc, nullptr, nullptr, Cv, row0, wid, lane);
}

// ---------------- gather: warp/node, 16 lanes x 16B per row ----------------
__global__ void gather_kernel(const __half* __restrict__ m, __half* __restrict__ o) {
    int gw = (blockIdx.x * blockDim.x + threadIdx.x) >> 5;
    int lane = threadIdx.x & 31;
    PDL_WAIT();
    if (gw >= NN) return;
    int beg = g_off[gw], end = g_off[gw + 1];
    int h = lane >> 4, cl = lane & 15;
    const uint4* base = (const uint4*)m;   // row = 16 x uint4 (256 B)
    float acc[8];
#pragma unroll
    for (int j = 0; j < 8; j++) acc[j] = 0.f;

    int e = beg + h;
    for (; e + 6 < end; e += 8) {
        int s0 = g_csr[e], s1 = g_csr[e + 2], s2 = g_csr[e + 4], s3 = g_csr[e + 6];
        uint4 v0 = base[s0 * 16 + cl];
        uint4 v1 = base[s1 * 16 + cl];
        uint4 v2 = base[s2 * 16 + cl];
        uint4 v3 = base[s3 * 16 + cl];
        const uint4* vv[4] = {&v0, &v1, &v2, &v3};
#pragma unroll
        for (int q = 0; q < 4; q++) {
            const __half2* hp = (const __half2*)vv[q];
#pragma unroll
            for (int j = 0; j < 4; j++) {
                float2 f = __half22float2(hp[j]);
                acc[2 * j] += f.x; acc[2 * j + 1] += f.y;
            }
        }
    }
    for (; e < end; e += 2) {
        uint4 v = base[g_csr[e] * 16 + cl];
        const __half2* hp = (const __half2*)&v;
#pragma unroll
        for (int j = 0; j < 4; j++) {
            float2 f = __half22float2(hp[j]);
            acc[2 * j] += f.x; acc[2 * j + 1] += f.y;
        }
    }
#pragma unroll
    for (int j = 0; j < 8; j++)
        acc[j] += __shfl_xor_sync(0xffffffffu, acc[j], 16);
    if (h == 0) {
        uint4 r;
        ((__half2*)&r)[0] = __floats2half2_rn(acc[0], acc[1]);
        ((__half2*)&r)[1] = __floats2half2_rn(acc[2], acc[3]);
        ((__half2*)&r)[2] = __floats2half2_rn(acc[4], acc[5]);
        ((__half2*)&r)[3] = __floats2half2_rn(acc[6], acc[7]);
        ((uint4*)o)[gw * 16 + cl] = r;
    }
}

// ---------------- launch ----------------
extern "C" void kernel_launch(void* const* d_in, const int* in_sizes, int n_in,
                              void* d_out, int out_size) {
    const float* x    = (const float*)d_in[0];
    const void*  ei   = d_in[1];
    const float* W1   = (const float*)d_in[2];
    const float* b1   = (const float*)d_in[3];
    const float* W2   = (const float*)d_in[4];
    const float* b2   = (const float*)d_in[5];
    const float* Wout = (const float*)d_in[6];
    const float* bout = (const float*)d_in[7];
    float* out = (float*)d_out;

    __half *hA, *hB, *w1h, *w1l, *w2h, *w2l, *woh, *wol;
    float *bw1, *bw2;
    cudaGetSymbolAddress((void**)&hA, g_hA);
    cudaGetSymbolAddress((void**)&hB, g_hB);
    cudaGetSymbolAddress((void**)&w1h, g_w1h); cudaGetSymbolAddress((void**)&w1l, g_w1l);
    cudaGetSymbolAddress((void**)&w2h, g_w2h); cudaGetSymbolAddress((void**)&w2l, g_w2l);
    cudaGetSymbolAddress((void**)&woh, g_woh); cudaGetSymbolAddress((void**)&wol, g_wol);
    cudaGetSymbolAddress((void**)&bw1, g_bw1); cudaGetSymbolAddress((void**)&bw2, g_bw2);

    const int SMX   = 98304;
    const int SM128 = 32768 + 2 * 128 * 256;  // 98304
    const int SM64  = 32768 + 2 * 64 * 256;   // 65536
    static cudaStream_t s2 = nullptr;
    static cudaEvent_t evF = nullptr, evJ = nullptr, evJ2 = nullptr;
    if (!s2) {
        cudaFuncSetAttribute((const void*)gemm_x, cudaFuncAttributeMaxDynamicSharedMemorySize, SMX);
        cudaFuncSetAttribute((const void*)gemm_on<128, 1, 0>, cudaFuncAttributeMaxDynamicSharedMemorySize, SM128);
        cudaFuncSetAttribute((const void*)gemm_on<64, 2, 1>,  cudaFuncAttributeMaxDynamicSharedMemorySize, SM64);
        cudaStreamCreateWithFlags(&s2, cudaStreamNonBlocking);
        cudaEventCreateWithFlags(&evF, cudaEventDisableTiming);
        cudaEventCreateWithFlags(&evJ, cudaEventDisableTiming);
        cudaEventCreateWithFlags(&evJ2, cudaEventDisableTiming);
    }

    // PDL launch helper (attribute on the dependent/secondary kernel)
    cudaLaunchAttribute pdlAttr;
    pdlAttr.id = cudaLaunchAttributeProgrammaticStreamSerialization;
    pdlAttr.val.programmaticStreamSerializationAllowed = 1;
    auto cfg = [&](int grid, int block, size_t smem, cudaStream_t st) {
        cudaLaunchConfig_t c = {};
        c.gridDim = dim3(grid); c.blockDim = dim3(block);
        c.dynamicSmemBytes = smem; c.stream = st;
        c.attrs = &pdlAttr; c.numAttrs = 1;
        return c;
    };

    const int gx = (NN + 127) / 128;        // 391
    const int gg = (NN * 32 + 255) / 256;   // 6250
    const int ge = (EE + 255) / 256;        // 2344

    // fork: CSR build on side stream (PDL between consecutive kernels)
    cudaEventRecord(evF, 0);
    cudaStreamWaitEvent(s2, evF, 0);
    zero_detect_kernel<<<NB, 256, 0, s2>>>((const unsigned int*)ei);
    {
        cudaLaunchConfig_t c = cfg(ge, 256, 0, s2);
        cudaLaunchKernelEx(&c, hist_kernel, ei);
    }
    {
        cudaLaunchConfig_t c = cfg(NB, 256, 0, s2);
        cudaLaunchKernelEx(&c, offs_kernel);
    }
    {
        cudaLaunchConfig_t c = cfg(ge, 256, 0, s2);
        cudaLaunchKernelEx(&c, fill_kernel, ei);
    }
    cudaEventRecord(evJ, s2);          // gathers need off+csr only
    {
        cudaLaunchConfig_t c = cfg(NB, 256, 0, s2);
        cudaLaunchKernelEx(&c, adeg_kernel);
    }
    cudaEventRecord(evJ2, s2);         // EPI=1 gemms need adeg/degf

    // main stream: prep + head GEMM (CSR-independent)
    const int PREP = 32768 + DOUT * DD + 2 * DD;
    prep_all_kernel<<<(PREP + 255) / 256, 256>>>(W1, W2, Wout, b1, b2);
    {
        cudaLaunchConfig_t c = cfg(gx, 256, SMX, 0);
        cudaLaunchKernelEx(&c, gemm_x, x, (const __half*)w1h, (const __half*)w1l, (void*)hA);
    }

    cudaStreamWaitEvent(0, evJ, 0);    // CSR ready

    {
        cudaLaunchConfig_t c = cfg(gg, 256, 0, 0);
        cudaLaunchKernelEx(&c, gather_kernel, (const __half*)hA, hB);
    }
    {
        cudaLaunchConfig_t c = cfg(gg, 256, 0, 0);
        cudaLaunchKernelEx(&c, gather_kernel, (const __half*)hB, hA);
    }
    cudaStreamWaitEvent(0, evJ2, 0);   // adeg/degf ready
    {
        cudaLaunchConfig_t c = cfg(gx, 256, SM128, 0);
        cudaLaunchKernelEx(&c, gemm_on<128, 1, 0>, (const __half*)hA,
                           (const __half*)w1h, (const __half*)w1l,
                           (const float*)b1, (const float*)bw1, (void*)hB);
    }
    {
        cudaLaunchConfig_t c = cfg(gg, 256, 0, 0);
        cudaLaunchKernelEx(&c, gather_kernel, (const __half*)hB, hA);
    }
    {
        cudaLaunchConfig_t c = cfg(gg, 256, 0, 0);
        cudaLaunchKernelEx(&c, gather_kernel, (const __half*)hA, hB);
    }
    {
        cudaLaunchConfig_t c = cfg(gx, 256, SM128, 0);
        cudaLaunchKernelEx(&c, gemm_on<128, 1, 0>, (const __half*)hB,
                           (const __half*)w2h, (const __half*)w2l,
                           (const float*)b2, (const float*)bw2, (void*)hA);
    }
    {
        cudaLaunchConfig_t c = cfg(gx, 256, SM64, 0);
        cudaLaunchKernelEx(&c, gemm_on<64, 2, 1>, (const __half*)hA,
                           (const __half*)woh, (const __half*)wol,
                           (const float*)bout, (const float*)nullptr, (void*)out);
    }
}

// round 13
// speedup vs baseline: 1.1427x; 1.1427x over previous
#include <cuda_runtime.h>
#include <cuda_fp16.h>
#include <cstdint>

#define NN   50000
#define EE   600000
#define DD   128
#define DOUT 64
#define NB   ((NN + 255) / 256)   // 196

// ---------------- scratch ----------------
__device__ __half g_hA[(size_t)NN * DD];
__device__ __half g_hB[(size_t)NN * DD];
__device__ __half g_w1h[DD * DD], g_w1l[DD * DD];      // W1^T fp16 split
__device__ __half g_w2h[DD * DD], g_w2l[DD * DD];      // (W2^2)^T fp16 split
__device__ __half g_woh[DOUT * DD], g_wol[DOUT * DD];  // Wout^T fp16 split
__device__ float g_bw1[DD], g_bw2[DD];                 // b1@W1, b2@W2
__device__ float g_degf[NN], g_adeg[NN];
__device__ int g_deg[NN], g_cnt[NN], g_off[NN + 1];
__device__ int g_csr[EE];
__device__ int g_is64;

__device__ __forceinline__ uint32_t smem_u32(const void* p) {
    uint32_t a;
    asm("{ .reg .u64 t; cvta.to.shared.u64 t, %1; cvt.u32.u64 %0, t; }" : "=r"(a) : "l"(p));
    return a;
}

__device__ __forceinline__ int edge_idx(const void* ei, int which, int e) {
    if (g_is64) return (int)((const long long*)ei)[(size_t)which * EE + e];
    return ((const int*)ei)[which * EE + e];
}

// ---------------- CSR build (side stream) ----------------
__global__ void zero_detect_kernel(const unsigned int* __restrict__ w) {
    int i = blockIdx.x * blockDim.x + threadIdx.x;
    if (i < NN) { g_deg[i] = 0; g_cnt[i] = 0; }
    if (i == 0) {
        int is64 = 1;
        for (int j = 1; j < 128; j += 2)
            if (w[j] != 0u) { is64 = 0; break; }
        g_is64 = is64;
    }
}
// 4 edges per thread, loads batched for MLP
__global__ void hist_kernel(const void* ei) {
    int base = blockIdx.x * 1024 + threadIdx.x;
    int d[4];
#pragma unroll
    for (int k = 0; k < 4; k++) {
        int e = base + k * 256;
        d[k] = (e < EE) ? edge_idx(ei, 1, e) : -1;
    }
#pragma unroll
    for (int k = 0; k < 4; k++)
        if (d[k] >= 0) atomicAdd(&g_deg[d[k]], 1);
}
// offsets: each block sums its predecessor degrees directly
__global__ void offs_kernel() {
    __shared__ int sh[256];
    __shared__ int base_sh;
    int t = threadIdx.x, bid = blockIdx.x, i = bid * 256 + t;
    int s = 0;
    for (int j = t; j < bid * 256; j += 256) s += g_deg[j];
    sh[t] = s;
    __syncthreads();
    for (int d = 128; d > 0; d >>= 1) {
        if (t < d) sh[t] += sh[t + d];
        __syncthreads();
    }
    if (t == 0) base_sh = sh[0];
    __syncthreads();
    int v = (i < NN) ? g_deg[i] : 0;
    sh[t] = v;
    __syncthreads();
    for (int d = 1; d < 256; d <<= 1) {
        int u = (t >= d) ? sh[t - d] : 0;
        __syncthreads();
        sh[t] += u;
        __syncthreads();
    }
    if (i < NN) g_off[i] = base_sh + sh[t] - v;
    if (bid == gridDim.x - 1 && t == 255) g_off[NN] = EE;
}
// 4 edges per thread, batched loads
__global__ void fill_kernel(const void* ei) {
    int base = blockIdx.x * 1024 + threadIdx.x;
    int d[4], s[4], off[4];
#pragma unroll
    for (int k = 0; k < 4; k++) {
        int e = base + k * 256;
        if (e < EE) {
            d[k] = edge_idx(ei, 1, e);
            s[k] = edge_idx(ei, 0, e);
        } else d[k] = -1;
    }
#pragma unroll
    for (int k = 0; k < 4; k++)
        if (d[k] >= 0) off[k] = g_off[d[k]] + atomicAdd(&g_cnt[d[k]], 1);
#pragma unroll
    for (int k = 0; k < 4; k++)
        if (d[k] >= 0) g_csr[off[k]] = s[k];
}
__global__ void adeg_kernel() {
    int i = blockIdx.x * blockDim.x + threadIdx.x;
    if (i >= NN) return;
    int b = g_off[i], e = g_off[i + 1];
    float s = 0.f;
    for (int k = b; k < e; k++) s += (float)g_deg[g_csr[k]];
    g_adeg[i] = s;
    g_degf[i] = (float)(e - b);
}

// ---------------- fp16 split helper ----------------
__device__ __forceinline__ void split2h(float x, __half& h, __half& l) {
    h = __float2half(x);
    l = __float2half(x - __half2float(h));
}

// ---------------- prep: W1^T, (W2^2)^T, Wout^T fp16 splits + bW vectors ----------------
__global__ void prep_all_kernel(const float* __restrict__ W1, const float* __restrict__ W2,
                                const float* __restrict__ Wo, const float* __restrict__ b1,
                                const float* __restrict__ b2) {
    int i = blockIdx.x * blockDim.x + threadIdx.x;
    if (i < 16384) {
        int n = i >> 7, k = i & 127;
        split2h(W1[k * DD + n], g_w1h[i], g_w1l[i]);
    } else if (i < 32768) {
        int j = i - 16384;
        int n = j >> 7, k = j & 127;
        float s = 0.f;
        for (int t = 0; t < DD; t++) s += W2[k * DD + t] * W2[t * DD + n];
        split2h(s, g_w2h[j], g_w2l[j]);
    } else if (i < 32768 + DOUT * DD) {
        int j = i - 32768;
        int n = j >> 7, k = j & 127;
        split2h(Wo[k * DOUT + n], g_woh[j], g_wol[j]);
    } else if (i < 32768 + DOUT * DD + 2 * DD) {
        int c = i - (32768 + DOUT * DD);
        if (c < DD) {
            float s = 0.f;
            for (int k = 0; k < DD; k++) s += b1[k] * W1[k * DD + c];
            g_bw1[c] = s;
        } else {
            c -= DD;
            float s = 0.f;
            for (int k = 0; k < DD; k++) s += b2[k] * W2[k * DD + c];
            g_bw2[c] = s;
        }
    }
}

// ---------------- fp16 MMA core ----------------
template <int N>
__device__ __forceinline__ void mma_pass(uint32_t sb, uint32_t aoff, uint32_t boff,
                                         float (&acc)[N / 8][4], int wid, int lane) {
    constexpr int NW = N / 2, NF16 = NW / 16, NF8 = NW / 8;
    int wr = wid & 3, wc = wid >> 2, lr = lane & 7;
    int a_half = (lane >> 3) & 1, a_kc = lane >> 4;
    int b_kc = (lane >> 3) & 1, b_nh = lane >> 4;
#pragma unroll
    for (int ks = 0; ks < 8; ks++) {
        int c0 = ks * 2;
        uint32_t a[2][4];
#pragma unroll
        for (int mf = 0; mf < 2; mf++) {
            uint32_t addr = sb + aoff + (uint32_t)((wr * 32 + mf * 16 + a_half * 8 + lr) * 256)
                          + (uint32_t)(((c0 + a_kc) ^ lr) << 4);
            asm volatile("ldmatrix.sync.aligned.m8n8.x4.shared.b16 {%0,%1,%2,%3}, [%4];"
                : "=r"(a[mf][0]), "=r"(a[mf][1]), "=r"(a[mf][2]), "=r"(a[mf][3]) : "r"(addr));
        }
#pragma unroll
        for (int nf = 0; nf < NF16; nf++) {
            uint32_t addr = sb + boff + (uint32_t)((wc * NW + nf * 16 + b_nh * 8 + lr) * 256)
                          + (uint32_t)(((c0 + b_kc) ^ lr) << 4);
            uint32_t b0, b1r, b2r, b3;
            asm volatile("ldmatrix.sync.aligned.m8n8.x4.shared.b16 {%0,%1,%2,%3}, [%4];"
                : "=r"(b0), "=r"(b1r), "=r"(b2r), "=r"(b3) : "r"(addr));
#pragma unroll
            for (int mf = 0; mf < 2; mf++) {
                float* c = acc[mf * NF8 + 2 * nf];
                asm volatile("mma.sync.aligned.m16n8k16.row.col.f32.f16.f16.f32 "
                    "{%0,%1,%2,%3}, {%4,%5,%6,%7}, {%8,%9}, {%0,%1,%2,%3};"
                    : "+f"(c[0]), "+f"(c[1]), "+f"(c[2]), "+f"(c[3])
                    : "r"(a[mf][0]), "r"(a[mf][1]), "r"(a[mf][2]), "r"(a[mf][3]), "r"(b0), "r"(b1r));
                float* d = acc[mf * NF8 + 2 * nf + 1];
                asm volatile("mma.sync.aligned.m16n8k16.row.col.f32.f16.f16.f32 "
                    "{%0,%1,%2,%3}, {%4,%5,%6,%7}, {%8,%9}, {%0,%1,%2,%3};"
                    : "+f"(d[0]), "+f"(d[1]), "+f"(d[2]), "+f"(d[3])
                    : "r"(a[mf][0]), "r"(a[mf][1]), "r"(a[mf][2]), "r"(a[mf][3]), "r"(b2r), "r"(b3));
            }
        }
    }
}

template <int N>
__device__ __forceinline__ void stageB_at(char* smem, uint32_t boff,
                                          const __half* __restrict__ B, int tid) {
    for (int idx = tid; idx < N * 16; idx += 256) {
        int r = idx >> 4, ch = idx & 15;
        uint4 v = *(const uint4*)(B + r * DD + ch * 8);
        *(uint4*)(smem + boff + r * 256 + ((ch ^ (r & 7)) << 4)) = v;
    }
}

template <int N, int EPI, int OUTF>
__device__ __forceinline__ void epilogue(float (&acc)[N / 8][4],
                                         const float* __restrict__ bias,
                                         const float* __restrict__ bw,
                                         void* __restrict__ Cv, int row0,
                                         int wid, int lane) {
    constexpr int NW = N / 2, NF8 = NW / 8;
    int wr = wid & 3, wc = wid >> 2;
    int g = lane >> 2, tg = lane & 3;
#pragma unroll
    for (int mf = 0; mf < 2; mf++) {
        int r = row0 + wr * 32 + mf * 16 + g;
        float d0 = 0.f, a0 = 0.f, d1 = 0.f, a1 = 0.f;
        if (EPI == 1) {
            if (r < NN)     { d0 = g_degf[r];     a0 = g_adeg[r]; }
            if (r + 8 < NN) { d1 = g_degf[r + 8]; a1 = g_adeg[r + 8]; }
        }
#pragma unroll
        for (int n8 = 0; n8 < NF8; n8++) {
            int c = wc * NW + n8 * 8 + tg * 2;
            float* v = acc[mf * NF8 + n8];
            float o0x = v[0], o0y = v[1], o1x = v[2], o1y = v[3];
            if (EPI == 1) {
                float bwx = bw[c], bwy = bw[c + 1], bx = bias[c], by = bias[c + 1];
                o0x = fmaxf(o0x + a0 * bwx + d0 * bx, 0.f);
                o0y = fmaxf(o0y + a0 * bwy + d0 * by, 0.f);
                o1x = fmaxf(o1x + a1 * bwx + d1 * bx, 0.f);
                o1y = fmaxf(o1y + a1 * bwy + d1 * by, 0.f);
            } else if (EPI == 2) {
                float bx = bias[c], by = bias[c + 1];
                o0x += bx; o0y += by; o1x += bx; o1y += by;
            }
            if (OUTF) {
                float* C = (float*)Cv;
                if (r < NN)
                    *(float2*)(C + (size_t)r * N + c) = make_float2(o0x, o0y);
                if (r + 8 < NN)
                    *(float2*)(C + (size_t)(r + 8) * N + c) = make_float2(o1x, o1y);
            } else {
                __half* C = (__half*)Cv;
                if (r < NN)
                    *(__half2*)(C + (size_t)r * N + c) = __floats2half2_rn(o0x, o0y);
                if (r + 8 < NN)
                    *(__half2*)(C + (size_t)(r + 8) * N + c) = __floats2half2_rn(o1x, o1y);
            }
        }
    }
}

// ---------------- on-path GEMM: A fp16 native, B fp16 hi+lo (2 passes) ----------------
template <int N, int EPI, int OUTF>
__global__ void __launch_bounds__(256, 2) gemm_on(
    const __half* __restrict__ A,
    const __half* __restrict__ Bhi, const __half* __restrict__ Blo,
    const float* __restrict__ bias, const float* __restrict__ bw,
    void* __restrict__ Cv)
{
    extern __shared__ char smem[];
    uint32_t sb = smem_u32(smem);
    int tid = threadIdx.x, wid = tid >> 5, lane = tid & 31;
    int row0 = blockIdx.x * 128;

    for (int idx = tid; idx < 2048; idx += 256) {
        int r = idx >> 4, ch = idx & 15, grow = row0 + r;
        uint4 v = make_uint4(0, 0, 0, 0);
        if (grow < NN) v = *(const uint4*)(A + (size_t)grow * DD + ch * 8);
        *(uint4*)(smem + r * 256 + ((ch ^ (r & 7)) << 4)) = v;
    }
    stageB_at<N>(smem, 32768u, Bhi, tid);
    stageB_at<N>(smem, 32768u + N * 256, Blo, tid);
    __syncthreads();

    float acc[N / 8][4];
#pragma unroll
    for (int i = 0; i < N / 8; i++)
#pragma unroll
        for (int j = 0; j < 4; j++) acc[i][j] = 0.f;

    mma_pass<N>(sb, 0u, 32768u, acc, wid, lane);
    mma_pass<N>(sb, 0u, 32768u + N * 256, acc, wid, lane);

    epilogue<N, EPI, OUTF>(acc, bias, bw, Cv, row0, wid, lane);
}

// ---------------- head GEMM: fp32 X, fp16-split A (3 passes) ----------------
__global__ void __launch_bounds__(256, 2) gemm_x(
    const float* __restrict__ X,
    const __half* __restrict__ Bhi, const __half* __restrict__ Blo,
    void* __restrict__ Cv)
{
    extern __shared__ char smem[];
    constexpr int N = 128;
    uint32_t sb = smem_u32(smem);
    int tid = threadIdx.x, wid = tid >> 5, lane = tid & 31;
    int row0 = blockIdx.x * 128;

    for (int idx = tid; idx < 2048; idx += 256) {
        int r = idx >> 4, ch = idx & 15, grow = row0 + r;
        __half h[8], l[8];
        if (grow < NN) {
            const float* p = X + (size_t)grow * DD + ch * 8;
            float4 v0 = *(const float4*)p, v1 = *(const float4*)(p + 4);
            float f[8] = {v0.x, v0.y, v0.z, v0.w, v1.x, v1.y, v1.z, v1.w};
#pragma unroll
            for (int j = 0; j < 8; j++) split2h(f[j], h[j], l[j]);
        } else {
#pragma unroll
            for (int j = 0; j < 8; j++) { h[j] = __float2half(0.f); l[j] = h[j]; }
        }
        int off = r * 256 + ((ch ^ (r & 7)) << 4);
        *(uint4*)(smem + off) = *(uint4*)h;
        *(uint4*)(smem + 32768 + off) = *(uint4*)l;
    }
    stageB_at<N>(smem, 65536u, Bhi, tid);
    __syncthreads();

    float acc[N / 8][4];
#pragma unroll
    for (int i = 0; i < N / 8; i++)
#pragma unroll
        for (int j = 0; j < 4; j++) acc[i][j] = 0.f;

    mma_pass<N>(sb, 0u, 65536u, acc, wid, lane);
    mma_pass<N>(sb, 32768u, 65536u, acc, wid, lane);
    __syncthreads();
    stageB_at<N>(smem, 65536u, Blo, tid);
    __syncthreads();
    mma_pass<N>(sb, 0u, 65536u, acc, wid, lane);

    epilogue<N, 0, 0>(acc, nullptr, nullptr, Cv, row0, wid, lane);
}

// ---------------- gather: warp/node, 16 lanes x 16B per row ----------------
__global__ void gather_kernel(const __half* __restrict__ m, __half* __restrict__ o) {
    int gw = (blockIdx.x * blockDim.x + threadIdx.x) >> 5;
    int lane = threadIdx.x & 31;
    if (gw >= NN) return;
    int beg = g_off[gw], end = g_off[gw + 1];
    int h = lane >> 4, cl = lane & 15;
    const uint4* base = (const uint4*)m;   // row = 16 x uint4 (256 B)
    float acc[8];
#pragma unroll
    for (int j = 0; j < 8; j++) acc[j] = 0.f;

    int e = beg + h;
    // 4 edges per half-warp per iteration
    for (; e + 6 < end; e += 8) {
        int s0 = g_csr[e], s1 = g_csr[e + 2], s2 = g_csr[e + 4], s3 = g_csr[e + 6];
        uint4 v0 = base[s0 * 16 + cl];
        uint4 v1 = base[s1 * 16 + cl];
        uint4 v2 = base[s2 * 16 + cl];
        uint4 v3 = base[s3 * 16 + cl];
        const uint4* vv[4] = {&v0, &v1, &v2, &v3};
#pragma unroll
        for (int q = 0; q < 4; q++) {
            const __half2* hp = (const __half2*)vv[q];
#pragma unroll
            for (int j = 0; j < 4; j++) {
                float2 f = __half22float2(hp[j]);
                acc[2 * j] += f.x; acc[2 * j + 1] += f.y;
            }
        }
    }
    // 2 edges per half-warp
    if (e + 2 < end) {
        int s0 = g_csr[e], s1 = g_csr[e + 2];
        uint4 v0 = base[s0 * 16 + cl];
        uint4 v1 = base[s1 * 16 + cl];
        const uint4* vv[2] = {&v0, &v1};
#pragma unroll
        for (int q = 0; q < 2; q++) {
            const __half2* hp = (const __half2*)vv[q];
#pragma unroll
            for (int j = 0; j < 4; j++) {
                float2 f = __half22float2(hp[j]);
                acc[2 * j] += f.x; acc[2 * j + 1] += f.y;
            }
        }
        e += 4;
    }
    for (; e < end; e += 2) {
        uint4 v = base[g_csr[e] * 16 + cl];
        const __half2* hp = (const __half2*)&v;
#pragma unroll
        for (int j = 0; j < 4; j++) {
            float2 f = __half22float2(hp[j]);
            acc[2 * j] += f.x; acc[2 * j + 1] += f.y;
        }
    }
#pragma unroll
    for (int j = 0; j < 8; j++)
        acc[j] += __shfl_xor_sync(0xffffffffu, acc[j], 16);
    if (h == 0) {
        uint4 r;
        ((__half2*)&r)[0] = __floats2half2_rn(acc[0], acc[1]);
        ((__half2*)&r)[1] = __floats2half2_rn(acc[2], acc[3]);
        ((__half2*)&r)[2] = __floats2half2_rn(acc[4], acc[5]);
        ((__half2*)&r)[3] = __floats2half2_rn(acc[6], acc[7]);
        ((uint4*)o)[gw * 16 + cl] = r;
    }
}

// ---------------- launch ----------------
extern "C" void kernel_launch(void* const* d_in, const int* in_sizes, int n_in,
                              void* d_out, int out_size) {
    const float* x    = (const float*)d_in[0];
    const void*  ei   = d_in[1];
    const float* W1   = (const float*)d_in[2];
    const float* b1   = (const float*)d_in[3];
    const float* W2   = (const float*)d_in[4];
    const float* b2   = (const float*)d_in[5];
    const float* Wout = (const float*)d_in[6];
    const float* bout = (const float*)d_in[7];
    float* out = (float*)d_out;

    __half *hA, *hB, *w1h, *w1l, *w2h, *w2l, *woh, *wol;
    float *bw1, *bw2;
    cudaGetSymbolAddress((void**)&hA, g_hA);
    cudaGetSymbolAddress((void**)&hB, g_hB);
    cudaGetSymbolAddress((void**)&w1h, g_w1h); cudaGetSymbolAddress((void**)&w1l, g_w1l);
    cudaGetSymbolAddress((void**)&w2h, g_w2h); cudaGetSymbolAddress((void**)&w2l, g_w2l);
    cudaGetSymbolAddress((void**)&woh, g_woh); cudaGetSymbolAddress((void**)&wol, g_wol);
    cudaGetSymbolAddress((void**)&bw1, g_bw1); cudaGetSymbolAddress((void**)&bw2, g_bw2);

    const int SMX   = 98304;
    const int SM128 = 32768 + 2 * 128 * 256;  // 98304
    const int SM64  = 32768 + 2 * 64 * 256;   // 65536
    static cudaStream_t s2 = nullptr;
    static cudaEvent_t evF = nullptr, evJ = nullptr, evJ2 = nullptr;
    if (!s2) {
        cudaFuncSetAttribute((const void*)gemm_x, cudaFuncAttributeMaxDynamicSharedMemorySize, SMX);
        cudaFuncSetAttribute((const void*)gemm_on<128, 1, 0>, cudaFuncAttributeMaxDynamicSharedMemorySize, SM128);
        cudaFuncSetAttribute((const void*)gemm_on<64, 2, 1>,  cudaFuncAttributeMaxDynamicSharedMemorySize, SM64);
        cudaStreamCreateWithFlags(&s2, cudaStreamNonBlocking);
        cudaEventCreateWithFlags(&evF, cudaEventDisableTiming);
        cudaEventCreateWithFlags(&evJ, cudaEventDisableTiming);
        cudaEventCreateWithFlags(&evJ2, cudaEventDisableTiming);
    }

    const int gx = (NN + 127) / 128;         // 391
    const int gg = (NN * 32 + 255) / 256;    // 6250
    const int ge4 = (EE + 1023) / 1024;      // 586 (4 edges/thread)

    // fork: CSR build on side stream
    cudaEventRecord(evF, 0);
    cudaStreamWaitEvent(s2, evF, 0);
    zero_detect_kernel<<<NB, 256, 0, s2>>>((const unsigned int*)ei);
    hist_kernel<<<ge4, 256, 0, s2>>>(ei);
    offs_kernel<<<NB, 256, 0, s2>>>();
    fill_kernel<<<ge4, 256, 0, s2>>>(ei);
    cudaEventRecord(evJ, s2);          // gathers need off+csr only
    adeg_kernel<<<NB, 256, 0, s2>>>();
    cudaEventRecord(evJ2, s2);         // EPI=1 gemms need adeg/degf

    // main stream: prep + head GEMM (CSR-independent)
    const int PREP = 32768 + DOUT * DD + 2 * DD;
    prep_all_kernel<<<(PREP + 255) / 256, 256>>>(W1, W2, Wout, b1, b2);
    gemm_x<<<gx, 256, SMX>>>(x, w1h, w1l, hA);   // hA = x@W1 (fp16)

    cudaStreamWaitEvent(0, evJ, 0);    // CSR ready

    // layer 1: relu(A^2(xW1)W1 + adeg*(b1W1) + deg*b1)
    gather_kernel<<<gg, 256>>>(hA, hB);
    gather_kernel<<<gg, 256>>>(hB, hA);
    cudaStreamWaitEvent(0, evJ2, 0);   // adeg/degf ready
    gemm_on<128, 1, 0><<<gx, 256, SM128>>>(hA, w1h, w1l, b1, bw1, hB);
    // layer 2: relu(A^2(h)W2^2 + adeg*(b2W2) + deg*b2)
    gather_kernel<<<gg, 256>>>(hB, hA);
    gather_kernel<<<gg, 256>>>(hA, hB);
    gemm_on<128, 1, 0><<<gx, 256, SM128>>>(hB, w2h, w2l, b2, bw2, hA);
    // output projection
    gemm_on<64, 2, 1><<<gx, 256, SM64>>>(hA, woh, wol, bout, nullptr, out);
}

// round 14
// speedup vs baseline: 1.2015x; 1.0514x over previous
#include <cuda_runtime.h>
#include <cuda_fp16.h>
#include <cstdint>

#define NN   50000
#define EE   600000
#define DD   128
#define DOUT 64
#define NB   ((NN + 255) / 256)   // 196

// ---------------- scratch ----------------
__device__ __half g_hA[(size_t)NN * DD];
__device__ __half g_hB[(size_t)NN * DD];
__device__ __half g_w1h[DD * DD], g_w1l[DD * DD];      // W1^T fp16 split
__device__ __half g_w2h[DD * DD], g_w2l[DD * DD];      // (W2^2)^T fp16 split
__device__ __half g_woh[DOUT * DD], g_wol[DOUT * DD];  // Wout^T fp16 split
__device__ float g_bw1[DD], g_bw2[DD];                 // b1@W1, b2@W2
__device__ float g_degf[NN], g_adeg[NN];
__device__ int g_deg[NN], g_cnt[NN], g_off[NN + 1];
__device__ int g_csr[EE];
__device__ int g_is64;

__device__ __forceinline__ uint32_t smem_u32(const void* p) {
    uint32_t a;
    asm("{ .reg .u64 t; cvta.to.shared.u64 t, %1; cvt.u32.u64 %0, t; }" : "=r"(a) : "l"(p));
    return a;
}

__device__ __forceinline__ int edge_idx(const void* ei, int which, int e) {
    if (g_is64) return (int)((const long long*)ei)[(size_t)which * EE + e];
    return ((const int*)ei)[which * EE + e];
}

// ---------------- CSR build (two side streams) ----------------
__global__ void zero_detect_kernel(const unsigned int* __restrict__ w) {
    int i = blockIdx.x * blockDim.x + threadIdx.x;
    if (i < NN) { g_deg[i] = 0; g_cnt[i] = 0; }
    if (i == 0) {
        int is64 = 1;
        for (int j = 1; j < 128; j += 2)
            if (w[j] != 0u) { is64 = 0; break; }
        g_is64 = is64;
    }
}
// half-range histogram, 4 edges/thread batched
__global__ void hist_half(const void* ei, int lo, int hi) {
    int base = lo + blockIdx.x * 1024 + threadIdx.x;
    int d[4];
#pragma unroll
    for (int k = 0; k < 4; k++) {
        int e = base + k * 256;
        d[k] = (e < hi) ? edge_idx(ei, 1, e) : -1;
    }
#pragma unroll
    for (int k = 0; k < 4; k++)
        if (d[k] >= 0) atomicAdd(&g_deg[d[k]], 1);
}
// offsets: each block sums predecessor degrees directly
__global__ void offs_kernel() {
    __shared__ int sh[256];
    __shared__ int base_sh;
    int t = threadIdx.x, bid = blockIdx.x, i = bid * 256 + t;
    int s = 0;
    for (int j = t; j < bid * 256; j += 256) s += g_deg[j];
    sh[t] = s;
    __syncthreads();
    for (int d = 128; d > 0; d >>= 1) {
        if (t < d) sh[t] += sh[t + d];
        __syncthreads();
    }
    if (t == 0) base_sh = sh[0];
    __syncthreads();
    int v = (i < NN) ? g_deg[i] : 0;
    sh[t] = v;
    __syncthreads();
    for (int d = 1; d < 256; d <<= 1) {
        int u = (t >= d) ? sh[t - d] : 0;
        __syncthreads();
        sh[t] += u;
        __syncthreads();
    }
    if (i < NN) g_off[i] = base_sh + sh[t] - v;
    if (bid == gridDim.x - 1 && t == 255) g_off[NN] = EE;
}
// half-range fill, 4 edges/thread batched
__global__ void fill_half(const void* ei, int lo, int hi) {
    int base = lo + blockIdx.x * 1024 + threadIdx.x;
    int d[4], s[4], off[4];
#pragma unroll
    for (int k = 0; k < 4; k++) {
        int e = base + k * 256;
        if (e < hi) {
            d[k] = edge_idx(ei, 1, e);
            s[k] = edge_idx(ei, 0, e);
        } else d[k] = -1;
    }
#pragma unroll
    for (int k = 0; k < 4; k++)
        if (d[k] >= 0) off[k] = g_off[d[k]] + atomicAdd(&g_cnt[d[k]], 1);
#pragma unroll
    for (int k = 0; k < 4; k++)
        if (d[k] >= 0) g_csr[off[k]] = s[k];
}
__global__ void adeg_kernel() {
    int i = blockIdx.x * blockDim.x + threadIdx.x;
    if (i >= NN) return;
    int b = g_off[i], e = g_off[i + 1];
    float s = 0.f;
    for (int k = b; k < e; k++) s += (float)g_deg[g_csr[k]];
    g_adeg[i] = s;
    g_degf[i] = (float)(e - b);
}

// ---------------- fp16 split helper ----------------
__device__ __forceinline__ void split2h(float x, __half& h, __half& l) {
    h = __float2half(x);
    l = __float2half(x - __half2float(h));
}

// ---------------- prep ----------------
__global__ void prep_all_kernel(const float* __restrict__ W1, const float* __restrict__ W2,
                                const float* __restrict__ Wo, const float* __restrict__ b1,
                                const float* __restrict__ b2) {
    int i = blockIdx.x * blockDim.x + threadIdx.x;
    if (i < 16384) {
        int n = i >> 7, k = i & 127;
        split2h(W1[k * DD + n], g_w1h[i], g_w1l[i]);
    } else if (i < 32768) {
        int j = i - 16384;
        int n = j >> 7, k = j & 127;
        float s = 0.f;
        for (int t = 0; t < DD; t++) s += W2[k * DD + t] * W2[t * DD + n];
        split2h(s, g_w2h[j], g_w2l[j]);
    } else if (i < 32768 + DOUT * DD) {
        int j = i - 32768;
        int n = j >> 7, k = j & 127;
        split2h(Wo[k * DOUT + n], g_woh[j], g_wol[j]);
    } else if (i < 32768 + DOUT * DD + 2 * DD) {
        int c = i - (32768 + DOUT * DD);
        if (c < DD) {
            float s = 0.f;
            for (int k = 0; k < DD; k++) s += b1[k] * W1[k * DD + c];
            g_bw1[c] = s;
        } else {
            c -= DD;
            float s = 0.f;
            for (int k = 0; k < DD; k++) s += b2[k] * W2[k * DD + c];
            g_bw2[c] = s;
        }
    }
}

// ---------------- fp16 MMA core ----------------
template <int N>
__device__ __forceinline__ void mma_pass(uint32_t sb, uint32_t aoff, uint32_t boff,
                                         float (&acc)[N / 8][4], int wid, int lane) {
    constexpr int NW = N / 2, NF16 = NW / 16, NF8 = NW / 8;
    int wr = wid & 3, wc = wid >> 2, lr = lane & 7;
    int a_half = (lane >> 3) & 1, a_kc = lane >> 4;
    int b_kc = (lane >> 3) & 1, b_nh = lane >> 4;
#pragma unroll
    for (int ks = 0; ks < 8; ks++) {
        int c0 = ks * 2;
        uint32_t a[2][4];
#pragma unroll
        for (int mf = 0; mf < 2; mf++) {
            uint32_t addr = sb + aoff + (uint32_t)((wr * 32 + mf * 16 + a_half * 8 + lr) * 256)
                          + (uint32_t)(((c0 + a_kc) ^ lr) << 4);
            asm volatile("ldmatrix.sync.aligned.m8n8.x4.shared.b16 {%0,%1,%2,%3}, [%4];"
                : "=r"(a[mf][0]), "=r"(a[mf][1]), "=r"(a[mf][2]), "=r"(a[mf][3]) : "r"(addr));
        }
#pragma unroll
        for (int nf = 0; nf < NF16; nf++) {
            uint32_t addr = sb + boff + (uint32_t)((wc * NW + nf * 16 + b_nh * 8 + lr) * 256)
                          + (uint32_t)(((c0 + b_kc) ^ lr) << 4);
            uint32_t b0, b1r, b2r, b3;
            asm volatile("ldmatrix.sync.aligned.m8n8.x4.shared.b16 {%0,%1,%2,%3}, [%4];"
                : "=r"(b0), "=r"(b1r), "=r"(b2r), "=r"(b3) : "r"(addr));
#pragma unroll
            for (int mf = 0; mf < 2; mf++) {
                float* c = acc[mf * NF8 + 2 * nf];
                asm volatile("mma.sync.aligned.m16n8k16.row.col.f32.f16.f16.f32 "
                    "{%0,%1,%2,%3}, {%4,%5,%6,%7}, {%8,%9}, {%0,%1,%2,%3};"
                    : "+f"(c[0]), "+f"(c[1]), "+f"(c[2]), "+f"(c[3])
                    : "r"(a[mf][0]), "r"(a[mf][1]), "r"(a[mf][2]), "r"(a[mf][3]), "r"(b0), "r"(b1r));
                float* d = acc[mf * NF8 + 2 * nf + 1];
                asm volatile("mma.sync.aligned.m16n8k16.row.col.f32.f16.f16.f32 "
                    "{%0,%1,%2,%3}, {%4,%5,%6,%7}, {%8,%9}, {%0,%1,%2,%3};"
                    : "+f"(d[0]), "+f"(d[1]), "+f"(d[2]), "+f"(d[3])
                    : "r"(a[mf][0]), "r"(a[mf][1]), "r"(a[mf][2]), "r"(a[mf][3]), "r"(b2r), "r"(b3));
            }
        }
    }
}

template <int N>
__device__ __forceinline__ void stageB_at(char* smem, uint32_t boff,
                                          const __half* __restrict__ B, int tid) {
    for (int idx = tid; idx < N * 16; idx += 256) {
        int r = idx >> 4, ch = idx & 15;
        uint4 v = *(const uint4*)(B + r * DD + ch * 8);
        *(uint4*)(smem + boff + r * 256 + ((ch ^ (r & 7)) << 4)) = v;
    }
}

template <int N, int EPI, int OUTF>
__device__ __forceinline__ void epilogue(float (&acc)[N / 8][4],
                                         const float* __restrict__ bias,
                                         const float* __restrict__ bw,
                                         void* __restrict__ Cv, int row0,
                                         int wid, int lane) {
    constexpr int NW = N / 2, NF8 = NW / 8;
    int wr = wid & 3, wc = wid >> 2;
    int g = lane >> 2, tg = lane & 3;
#pragma unroll
    for (int mf = 0; mf < 2; mf++) {
        int r = row0 + wr * 32 + mf * 16 + g;
        float d0 = 0.f, a0 = 0.f, d1 = 0.f, a1 = 0.f;
        if (EPI == 1) {
            if (r < NN)     { d0 = g_degf[r];     a0 = g_adeg[r]; }
            if (r + 8 < NN) { d1 = g_degf[r + 8]; a1 = g_adeg[r + 8]; }
        }
#pragma unroll
        for (int n8 = 0; n8 < NF8; n8++) {
            int c = wc * NW + n8 * 8 + tg * 2;
            float* v = acc[mf * NF8 + n8];
            float o0x = v[0], o0y = v[1], o1x = v[2], o1y = v[3];
            if (EPI == 1) {
                float bwx = bw[c], bwy = bw[c + 1], bx = bias[c], by = bias[c + 1];
                o0x = fmaxf(o0x + a0 * bwx + d0 * bx, 0.f);
                o0y = fmaxf(o0y + a0 * bwy + d0 * by, 0.f);
                o1x = fmaxf(o1x + a1 * bwx + d1 * bx, 0.f);
                o1y = fmaxf(o1y + a1 * bwy + d1 * by, 0.f);
            } else if (EPI == 2) {
                float bx = bias[c], by = bias[c + 1];
                o0x += bx; o0y += by; o1x += bx; o1y += by;
            }
            if (OUTF) {
                float* C = (float*)Cv;
                if (r < NN)
                    *(float2*)(C + (size_t)r * N + c) = make_float2(o0x, o0y);
                if (r + 8 < NN)
                    *(float2*)(C + (size_t)(r + 8) * N + c) = make_float2(o1x, o1y);
            } else {
                __half* C = (__half*)Cv;
                if (r < NN)
                    *(__half2*)(C + (size_t)r * N + c) = __floats2half2_rn(o0x, o0y);
                if (r + 8 < NN)
                    *(__half2*)(C + (size_t)(r + 8) * N + c) = __floats2half2_rn(o1x, o1y);
            }
        }
    }
}

// ---------------- on-path GEMM: A fp16 native, B fp16 hi+lo (2 passes) ----------------
template <int N, int EPI, int OUTF>
__global__ void __launch_bounds__(256, 2) gemm_on(
    const __half* __restrict__ A,
    const __half* __restrict__ Bhi, const __half* __restrict__ Blo,
    const float* __restrict__ bias, const float* __restrict__ bw,
    void* __restrict__ Cv)
{
    extern __shared__ char smem[];
    uint32_t sb = smem_u32(smem);
    int tid = threadIdx.x, wid = tid >> 5, lane = tid & 31;
    int row0 = blockIdx.x * 128;

    for (int idx = tid; idx < 2048; idx += 256) {
        int r = idx >> 4, ch = idx & 15, grow = row0 + r;
        uint4 v = make_uint4(0, 0, 0, 0);
        if (grow < NN) v = *(const uint4*)(A + (size_t)grow * DD + ch * 8);
        *(uint4*)(smem + r * 256 + ((ch ^ (r & 7)) << 4)) = v;
    }
    stageB_at<N>(smem, 32768u, Bhi, tid);
    stageB_at<N>(smem, 32768u + N * 256, Blo, tid);
    __syncthreads();

    float acc[N / 8][4];
#pragma unroll
    for (int i = 0; i < N / 8; i++)
#pragma unroll
        for (int j = 0; j < 4; j++) acc[i][j] = 0.f;

    mma_pass<N>(sb, 0u, 32768u, acc, wid, lane);
    mma_pass<N>(sb, 0u, 32768u + N * 256, acc, wid, lane);

    epilogue<N, EPI, OUTF>(acc, bias, bw, Cv, row0, wid, lane);
}

// ---------------- FUSED layer-2 GEMM + output projection ----------------
// Phase 1: m = A_feat @ (W2^2)^T, rowbias+relu in registers.
// Phase 2: write relu'd tile (fp16) into smem A region, restage Wout planes,
//          run N=64 MMA, write fp32 out.
__global__ void __launch_bounds__(256, 2) gemm_fused_out(
    const __half* __restrict__ A,
    const __half* __restrict__ Bhi, const __half* __restrict__ Blo,   // (W2^2)^T planes
    const float* __restrict__ bias, const float* __restrict__ bw,     // b2, b2@W2
    const __half* __restrict__ Whi, const __half* __restrict__ Wlo,   // Wout^T planes
    const float* __restrict__ bout, float* __restrict__ out)
{
    extern __shared__ char smem[];
    uint32_t sb = smem_u32(smem);
    int tid = threadIdx.x, wid = tid >> 5, lane = tid & 31;
    int row0 = blockIdx.x * 128;

    // ---- phase 1: layer-2 GEMM (N=128) ----
    for (int idx = tid; idx < 2048; idx += 256) {
        int r = idx >> 4, ch = idx & 15, grow = row0 + r;
        uint4 v = make_uint4(0, 0, 0, 0);
        if (grow < NN) v = *(const uint4*)(A + (size_t)grow * DD + ch * 8);
        *(uint4*)(smem + r * 256 + ((ch ^ (r & 7)) << 4)) = v;
    }
    stageB_at<128>(smem, 32768u, Bhi, tid);
    stageB_at<128>(smem, 32768u + 128 * 256, Blo, tid);
    __syncthreads();

    float acc[16][4];
#pragma unroll
    for (int i = 0; i < 16; i++)
#pragma unroll
        for (int j = 0; j < 4; j++) acc[i][j] = 0.f;

    mma_pass<128>(sb, 0u, 32768u, acc, wid, lane);
    mma_pass<128>(sb, 0u, 32768u + 128 * 256, acc, wid, lane);

    // rowbias + relu in registers, then store fp16 tile into smem A region
    __syncthreads();   // everyone done reading A/B planes
    {
        int wr = wid & 3, wc = wid >> 2;
        int g = lane >> 2, tg = lane & 3;
#pragma unroll
        for (int mf = 0; mf < 2; mf++) {
            int r0 = wr * 32 + mf * 16 + g;        // local row
            int gr0 = row0 + r0, gr1 = gr0 + 8;
            float d0 = (gr0 < NN) ? g_degf[gr0] : 0.f;
            float a0 = (gr0 < NN) ? g_adeg[gr0] : 0.f;
            float d1 = (gr1 < NN) ? g_degf[gr1] : 0.f;
            float a1 = (gr1 < NN) ? g_adeg[gr1] : 0.f;
#pragma unroll
            for (int n8 = 0; n8 < 8; n8++) {
                int c = wc * 64 + n8 * 8 + tg * 2;
                float bwx = bw[c], bwy = bw[c + 1], bx = bias[c], by = bias[c + 1];
                float* v = acc[mf * 8 + n8];
                float o0x = fmaxf(v[0] + a0 * bwx + d0 * bx, 0.f);
                float o0y = fmaxf(v[1] + a0 * bwy + d0 * by, 0.f);
                float o1x = fmaxf(v[2] + a1 * bwx + d1 * bx, 0.f);
                float o1y = fmaxf(v[3] + a1 * bwy + d1 * by, 0.f);
                int ch = c >> 3;
                int inb = (c & 7) * 2;             // byte within 16B chunk
                int off0 = r0 * 256 + ((ch ^ (r0 & 7)) << 4) + inb;
                int r1 = r0 + 8;
                int off1 = r1 * 256 + ((ch ^ (r1 & 7)) << 4) + inb;
                *(__half2*)(smem + off0) = __floats2half2_rn(o0x, o0y);
                *(__half2*)(smem + off1) = __floats2half2_rn(o1x, o1y);
            }
        }
    }
    // restage Wout planes over B region
    stageB_at<64>(smem, 32768u, Whi, tid);
    stageB_at<64>(smem, 32768u + 64 * 256, Wlo, tid);
    __syncthreads();

    // ---- phase 2: output GEMM (N=64) ----
    float acc2[8][4];
#pragma unroll
    for (int i = 0; i < 8; i++)
#pragma unroll
        for (int j = 0; j < 4; j++) acc2[i][j] = 0.f;

    mma_pass<64>(sb, 0u, 32768u, acc2, wid, lane);
    mma_pass<64>(sb, 0u, 32768u + 64 * 256, acc2, wid, lane);

    epilogue<64, 2, 1>(acc2, bout, nullptr, (void*)out, row0, wid, lane);
}

// ---------------- head GEMM: fp32 X, fp16-split A (3 passes) ----------------
__global__ void __launch_bounds__(256, 2) gemm_x(
    const float* __restrict__ X,
    const __half* __restrict__ Bhi, const __half* __restrict__ Blo,
    void* __restrict__ Cv)
{
    extern __shared__ char smem[];
    constexpr int N = 128;
    uint32_t sb = smem_u32(smem);
    int tid = threadIdx.x, wid = tid >> 5, lane = tid & 31;
    int row0 = blockIdx.x * 128;

    for (int idx = tid; idx < 2048; idx += 256) {
        int r = idx >> 4, ch = idx & 15, grow = row0 + r;
        __half h[8], l[8];
        if (grow < NN) {
            const float* p = X + (size_t)grow * DD + ch * 8;
            float4 v0 = *(const float4*)p, v1 = *(const float4*)(p + 4);
            float f[8] = {v0.x, v0.y, v0.z, v0.w, v1.x, v1.y, v1.z, v1.w};
#pragma unroll
            for (int j = 0; j < 8; j++) split2h(f[j], h[j], l[j]);
        } else {
#pragma unroll
            for (int j = 0; j < 8; j++) { h[j] = __float2half(0.f); l[j] = h[j]; }
        }
        int off = r * 256 + ((ch ^ (r & 7)) << 4);
        *(uint4*)(smem + off) = *(uint4*)h;
        *(uint4*)(smem + 32768 + off) = *(uint4*)l;
    }
    stageB_at<N>(smem, 65536u, Bhi, tid);
    __syncthreads();

    float acc[N / 8][4];
#pragma unroll
    for (int i = 0; i < N / 8; i++)
#pragma unroll
        for (int j = 0; j < 4; j++) acc[i][j] = 0.f;

    mma_pass<N>(sb, 0u, 65536u, acc, wid, lane);
    mma_pass<N>(sb, 32768u, 65536u, acc, wid, lane);
    __syncthreads();
    stageB_at<N>(smem, 65536u, Blo, tid);
    __syncthreads();
    mma_pass<N>(sb, 0u, 65536u, acc, wid, lane);

    epilogue<N, 0, 0>(acc, nullptr, nullptr, Cv, row0, wid, lane);
}

// ---------------- gather: warp/node, 16 lanes x 16B per row ----------------
__global__ void gather_kernel(const __half* __restrict__ m, __half* __restrict__ o) {
    int gw = (blockIdx.x * blockDim.x + threadIdx.x) >> 5;
    int lane = threadIdx.x & 31;
    if (gw >= NN) return;
    int beg = g_off[gw], end = g_off[gw + 1];
    int h = lane >> 4, cl = lane & 15;
    const uint4* base = (const uint4*)m;
    float acc[8];
#pragma unroll
    for (int j = 0; j < 8; j++) acc[j] = 0.f;

    int e = beg + h;
    for (; e + 6 < end; e += 8) {
        int s0 = g_csr[e], s1 = g_csr[e + 2], s2 = g_csr[e + 4], s3 = g_csr[e + 6];
        uint4 v0 = base[s0 * 16 + cl];
        uint4 v1 = base[s1 * 16 + cl];
        uint4 v2 = base[s2 * 16 + cl];
        uint4 v3 = base[s3 * 16 + cl];
        const uint4* vv[4] = {&v0, &v1, &v2, &v3};
#pragma unroll
        for (int q = 0; q < 4; q++) {
            const __half2* hp = (const __half2*)vv[q];
#pragma unroll
            for (int j = 0; j < 4; j++) {
                float2 f = __half22float2(hp[j]);
                acc[2 * j] += f.x; acc[2 * j + 1] += f.y;
            }
        }
    }
    if (e + 2 < end) {
        int s0 = g_csr[e], s1 = g_csr[e + 2];
        uint4 v0 = base[s0 * 16 + cl];
        uint4 v1 = base[s1 * 16 + cl];
        const uint4* vv[2] = {&v0, &v1};
#pragma unroll
        for (int q = 0; q < 2; q++) {
            const __half2* hp = (const __half2*)vv[q];
#pragma unroll
            for (int j = 0; j < 4; j++) {
                float2 f = __half22float2(hp[j]);
                acc[2 * j] += f.x; acc[2 * j + 1] += f.y;
            }
        }
        e += 4;
    }
    for (; e < end; e += 2) {
        uint4 v = base[g_csr[e] * 16 + cl];
        const __half2* hp = (const __half2*)&v;
#pragma unroll
        for (int j = 0; j < 4; j++) {
            float2 f = __half22float2(hp[j]);
            acc[2 * j] += f.x; acc[2 * j + 1] += f.y;
        }
    }
#pragma unroll
    for (int j = 0; j < 8; j++)
        acc[j] += __shfl_xor_sync(0xffffffffu, acc[j], 16);
    if (h == 0) {
        uint4 r;
        ((__half2*)&r)[0] = __floats2half2_rn(acc[0], acc[1]);
        ((__half2*)&r)[1] = __floats2half2_rn(acc[2], acc[3]);
        ((__half2*)&r)[2] = __floats2half2_rn(acc[4], acc[5]);
        ((__half2*)&r)[3] = __floats2half2_rn(acc[6], acc[7]);
        ((uint4*)o)[gw * 16 + cl] = r;
    }
}

// ---------------- launch ----------------
extern "C" void kernel_launch(void* const* d_in, const int* in_sizes, int n_in,
                              void* d_out, int out_size) {
    const float* x    = (const float*)d_in[0];
    const void*  ei   = d_in[1];
    const float* W1   = (const float*)d_in[2];
    const float* b1   = (const float*)d_in[3];
    const float* W2   = (const float*)d_in[4];
    const float* b2   = (const float*)d_in[5];
    const float* Wout = (const float*)d_in[6];
    const float* bout = (const float*)d_in[7];
    float* out = (float*)d_out;

    __half *hA, *hB, *w1h, *w1l, *w2h, *w2l, *woh, *wol;
    float *bw1, *bw2;
    cudaGetSymbolAddress((void**)&hA, g_hA);
    cudaGetSymbolAddress((void**)&hB, g_hB);
    cudaGetSymbolAddress((void**)&w1h, g_w1h); cudaGetSymbolAddress((void**)&w1l, g_w1l);
    cudaGetSymbolAddress((void**)&w2h, g_w2h); cudaGetSymbolAddress((void**)&w2l, g_w2l);
    cudaGetSymbolAddress((void**)&woh, g_woh); cudaGetSymbolAddress((void**)&wol, g_wol);
    cudaGetSymbolAddress((void**)&bw1, g_bw1); cudaGetSymbolAddress((void**)&bw2, g_bw2);

    const int SMX   = 98304;
    const int SM128 = 32768 + 2 * 128 * 256;  // 98304
    static cudaStream_t s2 = nullptr, s3 = nullptr;
    static cudaEvent_t evF = nullptr, evZ = nullptr, evH = nullptr,
                       evO = nullptr, evFl = nullptr, evJ = nullptr, evJ2 = nullptr;
    if (!s2) {
        cudaFuncSetAttribute((const void*)gemm_x, cudaFuncAttributeMaxDynamicSharedMemorySize, SMX);
        cudaFuncSetAttribute((const void*)gemm_on<128, 1, 0>, cudaFuncAttributeMaxDynamicSharedMemorySize, SM128);
        cudaFuncSetAttribute((const void*)gemm_fused_out, cudaFuncAttributeMaxDynamicSharedMemorySize, SM128);
        cudaStreamCreateWithFlags(&s2, cudaStreamNonBlocking);
        cudaStreamCreateWithFlags(&s3, cudaStreamNonBlocking);
        cudaEventCreateWithFlags(&evF, cudaEventDisableTiming);
        cudaEventCreateWithFlags(&evZ, cudaEventDisableTiming);
        cudaEventCreateWithFlags(&evH, cudaEventDisableTiming);
        cudaEventCreateWithFlags(&evO, cudaEventDisableTiming);
        cudaEventCreateWithFlags(&evFl, cudaEventDisableTiming);
        cudaEventCreateWithFlags(&evJ, cudaEventDisableTiming);
        cudaEventCreateWithFlags(&evJ2, cudaEventDisableTiming);
    }

    const int gx = (NN + 127) / 128;         // 391
    const int gg = (NN * 32 + 255) / 256;    // 6250
    const int HALF = EE / 2;                 // 300000
    const int geh = (HALF + 1023) / 1024;    // 293

    // fork: CSR build on two side streams
    cudaEventRecord(evF, 0);
    cudaStreamWaitEvent(s2, evF, 0);
    zero_detect_kernel<<<NB, 256, 0, s2>>>((const unsigned int*)ei);
    cudaEventRecord(evZ, s2);
    cudaStreamWaitEvent(s3, evZ, 0);
    hist_half<<<geh, 256, 0, s2>>>(ei, 0, HALF);
    hist_half<<<geh, 256, 0, s3>>>(ei, HALF, EE);
    cudaEventRecord(evH, s3);
    cudaStreamWaitEvent(s2, evH, 0);
    offs_kernel<<<NB, 256, 0, s2>>>();
    cudaEventRecord(evO, s2);
    cudaStreamWaitEvent(s3, evO, 0);
    fill_half<<<geh, 256, 0, s2>>>(ei, 0, HALF);
    fill_half<<<geh, 256, 0, s3>>>(ei, HALF, EE);
    cudaEventRecord(evFl, s3);
    cudaStreamWaitEvent(s2, evFl, 0);
    cudaEventRecord(evJ, s2);          // gathers need off+csr
    adeg_kernel<<<NB, 256, 0, s2>>>();
    cudaEventRecord(evJ2, s2);         // rowbias gemms need adeg/degf

    // main stream: prep + head GEMM (CSR-independent)
    const int PREP = 32768 + DOUT * DD + 2 * DD;
    prep_all_kernel<<<(PREP + 255) / 256, 256>>>(W1, W2, Wout, b1, b2);
    gemm_x<<<gx, 256, SMX>>>(x, w1h, w1l, hA);   // hA = x@W1 (fp16)

    cudaStreamWaitEvent(0, evJ, 0);    // CSR ready

    // layer 1: relu(A^2(xW1)W1 + adeg*(b1W1) + deg*b1)
    gather_kernel<<<gg, 256>>>(hA, hB);
    gather_kernel<<<gg, 256>>>(hB, hA);
    cudaStreamWaitEvent(0, evJ2, 0);   // adeg/degf ready
    gemm_on<128, 1, 0><<<gx, 256, SM128>>>(hA, w1h, w1l, b1, bw1, hB);
    // layer 2 + output projection (fused)
    gather_kernel<<<gg, 256>>>(hB, hA);
    gather_kernel<<<gg, 256>>>(hA, hB);
    gemm_fused_out<<<gx, 256, SM128>>>(hB, w2h, w2l, b2, bw2, woh, wol, bout, out);
}

// round 15
// speedup vs baseline: 1.3996x; 1.1649x over previous
#include <cuda_runtime.h>
#include <cuda_fp16.h>
#include <cstdint>

#define NN   50000
#define EE   600000
#define DD   128
#define DOUT 64
#define NB   ((NN + 255) / 256)   // 196

// ---------------- scratch ----------------
__device__ __half g_hA[(size_t)NN * DD];
__device__ __half g_hB[(size_t)NN * DD];
__device__ __half g_w1h[DD * DD], g_w1l[DD * DD];      // (W1^2)^T fp16 split
__device__ __half g_w2h[DD * DD], g_w2l[DD * DD];      // (W2^2)^T fp16 split
__device__ __half g_woh[DOUT * DD], g_wol[DOUT * DD];  // Wout^T fp16 split
__device__ float g_bw1[DD], g_bw2[DD];                 // b1@W1, b2@W2
__device__ float g_degf[NN], g_adeg[NN];
__device__ int g_deg[NN], g_cnt[NN], g_off[NN + 1];
__device__ int g_part[NB];
__device__ int g_csr[EE];
__device__ int g_is64;

__device__ __forceinline__ uint32_t smem_u32(const void* p) {
    uint32_t a;
    asm("{ .reg .u64 t; cvta.to.shared.u64 t, %1; cvt.u32.u64 %0, t; }" : "=r"(a) : "l"(p));
    return a;
}

__device__ __forceinline__ int edge_idx(const void* ei, int which, int e) {
    if (g_is64) return (int)((const long long*)ei)[(size_t)which * EE + e];
    return ((const int*)ei)[which * EE + e];
}

// ---------------- CSR build (two side streams) ----------------
__global__ void zero_detect_kernel(const unsigned int* __restrict__ w) {
    int i = blockIdx.x * blockDim.x + threadIdx.x;
    if (i < NN) { g_deg[i] = 0; g_cnt[i] = 0; }
    if (i == 0) {
        int is64 = 1;
        for (int j = 1; j < 128; j += 2)
            if (w[j] != 0u) { is64 = 0; break; }
        g_is64 = is64;
    }
}
__global__ void hist_half(const void* ei, int lo, int hi) {
    int base = lo + blockIdx.x * 1024 + threadIdx.x;
    int d[4];
#pragma unroll
    for (int k = 0; k < 4; k++) {
        int e = base + k * 256;
        d[k] = (e < hi) ? edge_idx(ei, 1, e) : -1;
    }
#pragma unroll
    for (int k = 0; k < 4; k++)
        if (d[k] >= 0) atomicAdd(&g_deg[d[k]], 1);
}
// per-block degree totals
__global__ void partial_kernel() {
    __shared__ int sh[256];
    int t = threadIdx.x, i = blockIdx.x * 256 + t;
    sh[t] = (i < NN) ? g_deg[i] : 0;
    __syncthreads();
    for (int d = 128; d > 0; d >>= 1) {
        if (t < d) sh[t] += sh[t + d];
        __syncthreads();
    }
    if (t == 0) g_part[blockIdx.x] = sh[0];
}
// offsets: block prefix from g_part (196 values), local scan
__global__ void offs_kernel() {
    __shared__ int sh[256];
    __shared__ int base_sh;
    int t = threadIdx.x, bid = blockIdx.x, i = bid * 256 + t;
    int pv = (t < bid) ? g_part[t] : 0;
    sh[t] = pv;
    __syncthreads();
    for (int d = 128; d > 0; d >>= 1) {
        if (t < d) sh[t] += sh[t + d];
        __syncthreads();
    }
    if (t == 0) base_sh = sh[0];
    __syncthreads();
    int v = (i < NN) ? g_deg[i] : 0;
    sh[t] = v;
    __syncthreads();
    for (int d = 1; d < 256; d <<= 1) {
        int u = (t >= d) ? sh[t - d] : 0;
        __syncthreads();
        sh[t] += u;
        __syncthreads();
    }
    if (i < NN) g_off[i] = base_sh + sh[t] - v;
    if (bid == gridDim.x - 1 && t == 255) g_off[NN] = EE;
}
__global__ void fill_half(const void* ei, int lo, int hi) {
    int base = lo + blockIdx.x * 1024 + threadIdx.x;
    int d[4], s[4], off[4];
#pragma unroll
    for (int k = 0; k < 4; k++) {
        int e = base + k * 256;
        if (e < hi) {
            d[k] = edge_idx(ei, 1, e);
            s[k] = edge_idx(ei, 0, e);
        } else d[k] = -1;
    }
#pragma unroll
    for (int k = 0; k < 4; k++)
        if (d[k] >= 0) off[k] = g_off[d[k]] + atomicAdd(&g_cnt[d[k]], 1);
#pragma unroll
    for (int k = 0; k < 4; k++)
        if (d[k] >= 0) g_csr[off[k]] = s[k];
}
__global__ void adeg_kernel() {
    int i = blockIdx.x * blockDim.x + threadIdx.x;
    if (i >= NN) return;
    int b = g_off[i], e = g_off[i + 1];
    float s = 0.f;
    for (int k = b; k < e; k++) s += (float)g_deg[g_csr[k]];
    g_adeg[i] = s;
    g_degf[i] = (float)(e - b);
}

// ---------------- fp16 split helper ----------------
__device__ __forceinline__ void split2h(float x, __half& h, __half& l) {
    h = __float2half(x);
    l = __float2half(x - __half2float(h));
}

// ---------------- prep: (W1^2)^T, (W2^2)^T, Wout^T fp16 splits + bW vectors ----------------
__global__ void prep_all_kernel(const float* __restrict__ W1, const float* __restrict__ W2,
                                const float* __restrict__ Wo, const float* __restrict__ b1,
                                const float* __restrict__ b2) {
    int i = blockIdx.x * blockDim.x + threadIdx.x;
    if (i < 16384) {                       // (W1*W1)^T
        int n = i >> 7, k = i & 127;
        float s = 0.f;
        for (int t = 0; t < DD; t++) s += W1[k * DD + t] * W1[t * DD + n];
        split2h(s, g_w1h[i], g_w1l[i]);
    } else if (i < 32768) {                // (W2*W2)^T
        int j = i - 16384;
        int n = j >> 7, k = j & 127;
        float s = 0.f;
        for (int t = 0; t < DD; t++) s += W2[k * DD + t] * W2[t * DD + n];
        split2h(s, g_w2h[j], g_w2l[j]);
    } else if (i < 32768 + DOUT * DD) {    // Wout^T
        int j = i - 32768;
        int n = j >> 7, k = j & 127;
        split2h(Wo[k * DOUT + n], g_woh[j], g_wol[j]);
    } else if (i < 32768 + DOUT * DD + 2 * DD) {
        int c = i - (32768 + DOUT * DD);
        if (c < DD) {
            float s = 0.f;
            for (int k = 0; k < DD; k++) s += b1[k] * W1[k * DD + c];
            g_bw1[c] = s;
        } else {
            c -= DD;
            float s = 0.f;
            for (int k = 0; k < DD; k++) s += b2[k] * W2[k * DD + c];
            g_bw2[c] = s;
        }
    }
}

// ---------------- convert x: fp32 -> fp16 ----------------
__global__ void conv_x_kernel(const float* __restrict__ X) {
    int i = blockIdx.x * blockDim.x + threadIdx.x;   // per 4 floats
    if (i >= NN * DD / 4) return;
    float4 v = ((const float4*)X)[i];
    uint2 r;
    *(__half2*)&r.x = __floats2half2_rn(v.x, v.y);
    *(__half2*)&r.y = __floats2half2_rn(v.z, v.w);
    ((uint2*)g_hA)[i] = r;
}

// ---------------- fp16 MMA core ----------------
template <int N>
__device__ __forceinline__ void mma_pass(uint32_t sb, uint32_t aoff, uint32_t boff,
                                         float (&acc)[N / 8][4], int wid, int lane) {
    constexpr int NW = N / 2, NF16 = NW / 16, NF8 = NW / 8;
    int wr = wid & 3, wc = wid >> 2, lr = lane & 7;
    int a_half = (lane >> 3) & 1, a_kc = lane >> 4;
    int b_kc = (lane >> 3) & 1, b_nh = lane >> 4;
#pragma unroll
    for (int ks = 0; ks < 8; ks++) {
        int c0 = ks * 2;
        uint32_t a[2][4];
#pragma unroll
        for (int mf = 0; mf < 2; mf++) {
            uint32_t addr = sb + aoff + (uint32_t)((wr * 32 + mf * 16 + a_half * 8 + lr) * 256)
                          + (uint32_t)(((c0 + a_kc) ^ lr) << 4);
            asm volatile("ldmatrix.sync.aligned.m8n8.x4.shared.b16 {%0,%1,%2,%3}, [%4];"
                : "=r"(a[mf][0]), "=r"(a[mf][1]), "=r"(a[mf][2]), "=r"(a[mf][3]) : "r"(addr));
        }
#pragma unroll
        for (int nf = 0; nf < NF16; nf++) {
            uint32_t addr = sb + boff + (uint32_t)((wc * NW + nf * 16 + b_nh * 8 + lr) * 256)
                          + (uint32_t)(((c0 + b_kc) ^ lr) << 4);
            uint32_t b0, b1r, b2r, b3;
            asm volatile("ldmatrix.sync.aligned.m8n8.x4.shared.b16 {%0,%1,%2,%3}, [%4];"
                : "=r"(b0), "=r"(b1r), "=r"(b2r), "=r"(b3) : "r"(addr));
#pragma unroll
            for (int mf = 0; mf < 2; mf++) {
                float* c = acc[mf * NF8 + 2 * nf];
                asm volatile("mma.sync.aligned.m16n8k16.row.col.f32.f16.f16.f32 "
                    "{%0,%1,%2,%3}, {%4,%5,%6,%7}, {%8,%9}, {%0,%1,%2,%3};"
                    : "+f"(c[0]), "+f"(c[1]), "+f"(c[2]), "+f"(c[3])
                    : "r"(a[mf][0]), "r"(a[mf][1]), "r"(a[mf][2]), "r"(a[mf][3]), "r"(b0), "r"(b1r));
                float* d = acc[mf * NF8 + 2 * nf + 1];
                asm volatile("mma.sync.aligned.m16n8k16.row.col.f32.f16.f16.f32 "
                    "{%0,%1,%2,%3}, {%4,%5,%6,%7}, {%8,%9}, {%0,%1,%2,%3};"
                    : "+f"(d[0]), "+f"(d[1]), "+f"(d[2]), "+f"(d[3])
                    : "r"(a[mf][0]), "r"(a[mf][1]), "r"(a[mf][2]), "r"(a[mf][3]), "r"(b2r), "r"(b3));
            }
        }
    }
}

template <int N>
__device__ __forceinline__ void stageB_at(char* smem, uint32_t boff,
                                          const __half* __restrict__ B, int tid) {
    for (int idx = tid; idx < N * 16; idx += 256) {
        int r = idx >> 4, ch = idx & 15;
        uint4 v = *(const uint4*)(B + r * DD + ch * 8);
        *(uint4*)(smem + boff + r * 256 + ((ch ^ (r & 7)) << 4)) = v;
    }
}

template <int N, int EPI, int OUTF>
__device__ __forceinline__ void epilogue(float (&acc)[N / 8][4],
                                         const float* __restrict__ bias,
                                         const float* __restrict__ bw,
                                         void* __restrict__ Cv, int row0,
                                         int wid, int lane) {
    constexpr int NW = N / 2, NF8 = NW / 8;
    int wr = wid & 3, wc = wid >> 2;
    int g = lane >> 2, tg = lane & 3;
#pragma unroll
    for (int mf = 0; mf < 2; mf++) {
        int r = row0 + wr * 32 + mf * 16 + g;
        float d0 = 0.f, a0 = 0.f, d1 = 0.f, a1 = 0.f;
        if (EPI == 1) {
            if (r < NN)     { d0 = g_degf[r];     a0 = g_adeg[r]; }
            if (r + 8 < NN) { d1 = g_degf[r + 8]; a1 = g_adeg[r + 8]; }
        }
#pragma unroll
        for (int n8 = 0; n8 < NF8; n8++) {
            int c = wc * NW + n8 * 8 + tg * 2;
            float* v = acc[mf * NF8 + n8];
            float o0x = v[0], o0y = v[1], o1x = v[2], o1y = v[3];
            if (EPI == 1) {
                float bwx = bw[c], bwy = bw[c + 1], bx = bias[c], by = bias[c + 1];
                o0x = fmaxf(o0x + a0 * bwx + d0 * bx, 0.f);
                o0y = fmaxf(o0y + a0 * bwy + d0 * by, 0.f);
                o1x = fmaxf(o1x + a1 * bwx + d1 * bx, 0.f);
                o1y = fmaxf(o1y + a1 * bwy + d1 * by, 0.f);
            } else if (EPI == 2) {
                float bx = bias[c], by = bias[c + 1];
                o0x += bx; o0y += by; o1x += bx; o1y += by;
            }
            if (OUTF) {
                float* C = (float*)Cv;
                if (r < NN)
                    *(float2*)(C + (size_t)r * N + c) = make_float2(o0x, o0y);
                if (r + 8 < NN)
                    *(float2*)(C + (size_t)(r + 8) * N + c) = make_float2(o1x, o1y);
            } else {
                __half* C = (__half*)Cv;
                if (r < NN)
                    *(__half2*)(C + (size_t)r * N + c) = __floats2half2_rn(o0x, o0y);
                if (r + 8 < NN)
                    *(__half2*)(C + (size_t)(r + 8) * N + c) = __floats2half2_rn(o1x, o1y);
            }
        }
    }
}

// ---------------- layer-1 GEMM: A fp16 native, B fp16 hi+lo, rowbias+relu epi ----------------
template <int N, int EPI, int OUTF>
__global__ void __launch_bounds__(256, 2) gemm_on(
    const __half* __restrict__ A,
    const __half* __restrict__ Bhi, const __half* __restrict__ Blo,
    const float* __restrict__ bias, const float* __restrict__ bw,
    void* __restrict__ Cv)
{
    extern __shared__ char smem[];
    uint32_t sb = smem_u32(smem);
    int tid = threadIdx.x, wid = tid >> 5, lane = tid & 31;
    int row0 = blockIdx.x * 128;

    for (int idx = tid; idx < 2048; idx += 256) {
        int r = idx >> 4, ch = idx & 15, grow = row0 + r;
        uint4 v = make_uint4(0, 0, 0, 0);
        if (grow < NN) v = *(const uint4*)(A + (size_t)grow * DD + ch * 8);
        *(uint4*)(smem + r * 256 + ((ch ^ (r & 7)) << 4)) = v;
    }
    stageB_at<N>(smem, 32768u, Bhi, tid);
    stageB_at<N>(smem, 32768u + N * 256, Blo, tid);
    __syncthreads();

    float acc[N / 8][4];
#pragma unroll
    for (int i = 0; i < N / 8; i++)
#pragma unroll
        for (int j = 0; j < 4; j++) acc[i][j] = 0.f;

    mma_pass<N>(sb, 0u, 32768u, acc, wid, lane);
    mma_pass<N>(sb, 0u, 32768u + N * 256, acc, wid, lane);

    epilogue<N, EPI, OUTF>(acc, bias, bw, Cv, row0, wid, lane);
}

// ---------------- FUSED layer-2 GEMM + output projection ----------------
__global__ void __launch_bounds__(256, 2) gemm_fused_out(
    const __half* __restrict__ A,
    const __half* __restrict__ Bhi, const __half* __restrict__ Blo,   // (W2^2)^T planes
    const float* __restrict__ bias, const float* __restrict__ bw,     // b2, b2@W2
    const __half* __restrict__ Whi, const __half* __restrict__ Wlo,   // Wout^T planes
    const float* __restrict__ bout, float* __restrict__ out)
{
    extern __shared__ char smem[];
    uint32_t sb = smem_u32(smem);
    int tid = threadIdx.x, wid = tid >> 5, lane = tid & 31;
    int row0 = blockIdx.x * 128;

    for (int idx = tid; idx < 2048; idx += 256) {
        int r = idx >> 4, ch = idx & 15, grow = row0 + r;
        uint4 v = make_uint4(0, 0, 0, 0);
        if (grow < NN) v = *(const uint4*)(A + (size_t)grow * DD + ch * 8);
        *(uint4*)(smem + r * 256 + ((ch ^ (r & 7)) << 4)) = v;
    }
    stageB_at<128>(smem, 32768u, Bhi, tid);
    stageB_at<128>(smem, 32768u + 128 * 256, Blo, tid);
    __syncthreads();

    float acc[16][4];
#pragma unroll
    for (int i = 0; i < 16; i++)
#pragma unroll
        for (int j = 0; j < 4; j++) acc[i][j] = 0.f;

    mma_pass<128>(sb, 0u, 32768u, acc, wid, lane);
    mma_pass<128>(sb, 0u, 32768u + 128 * 256, acc, wid, lane);

    __syncthreads();
    {
        int wr = wid & 3, wc = wid >> 2;
        int g = lane >> 2, tg = lane & 3;
#pragma unroll
        for (int mf = 0; mf < 2; mf++) {
            int r0 = wr * 32 + mf * 16 + g;
            int gr0 = row0 + r0, gr1 = gr0 + 8;
            float d0 = (gr0 < NN) ? g_degf[gr0] : 0.f;
            float a0 = (gr0 < NN) ? g_adeg[gr0] : 0.f;
            float d1 = (gr1 < NN) ? g_degf[gr1] : 0.f;
            float a1 = (gr1 < NN) ? g_adeg[gr1] : 0.f;
#pragma unroll
            for (int n8 = 0; n8 < 8; n8++) {
                int c = wc * 64 + n8 * 8 + tg * 2;
                float bwx = bw[c], bwy = bw[c + 1], bx = bias[c], by = bias[c + 1];
                float* v = acc[mf * 8 + n8];
                float o0x = fmaxf(v[0] + a0 * bwx + d0 * bx, 0.f);
                float o0y = fmaxf(v[1] + a0 * bwy + d0 * by, 0.f);
                float o1x = fmaxf(v[2] + a1 * bwx + d1 * bx, 0.f);
                float o1y = fmaxf(v[3] + a1 * bwy + d1 * by, 0.f);
                int ch = c >> 3;
                int inb = (c & 7) * 2;
                int off0 = r0 * 256 + ((ch ^ (r0 & 7)) << 4) + inb;
                int r1 = r0 + 8;
                int off1 = r1 * 256 + ((ch ^ (r1 & 7)) << 4) + inb;
                *(__half2*)(smem + off0) = __floats2half2_rn(o0x, o0y);
                *(__half2*)(smem + off1) = __floats2half2_rn(o1x, o1y);
            }
        }
    }
    stageB_at<64>(smem, 32768u, Whi, tid);
    stageB_at<64>(smem, 32768u + 64 * 256, Wlo, tid);
    __syncthreads();

    float acc2[8][4];
#pragma unroll
    for (int i = 0; i < 8; i++)
#pragma unroll
        for (int j = 0; j < 4; j++) acc2[i][j] = 0.f;

    mma_pass<64>(sb, 0u, 32768u, acc2, wid, lane);
    mma_pass<64>(sb, 0u, 32768u + 64 * 256, acc2, wid, lane);

    epilogue<64, 2, 1>(acc2, bout, nullptr, (void*)out, row0, wid, lane);
}

// ---------------- gather: warp/node, 16 lanes x 16B per row ----------------
__global__ void gather_kernel(const __half* __restrict__ m, __half* __restrict__ o) {
    int gw = (blockIdx.x * blockDim.x + threadIdx.x) >> 5;
    int lane = threadIdx.x & 31;
    if (gw >= NN) return;
    int beg = g_off[gw], end = g_off[gw + 1];
    int h = lane >> 4, cl = lane & 15;
    const uint4* base = (const uint4*)m;
    float acc[8];
#pragma unroll
    for (int j = 0; j < 8; j++) acc[j] = 0.f;

    int e = beg + h;
    for (; e + 6 < end; e += 8) {
        int s0 = g_csr[e], s1 = g_csr[e + 2], s2 = g_csr[e + 4], s3 = g_csr[e + 6];
        uint4 v0 = base[s0 * 16 + cl];
        uint4 v1 = base[s1 * 16 + cl];
        uint4 v2 = base[s2 * 16 + cl];
        uint4 v3 = base[s3 * 16 + cl];
        const uint4* vv[4] = {&v0, &v1, &v2, &v3};
#pragma unroll
        for (int q = 0; q < 4; q++) {
            const __half2* hp = (const __half2*)vv[q];
#pragma unroll
            for (int j = 0; j < 4; j++) {
                float2 f = __half22float2(hp[j]);
                acc[2 * j] += f.x; acc[2 * j + 1] += f.y;
            }
        }
    }
    if (e + 2 < end) {
        int s0 = g_csr[e], s1 = g_csr[e + 2];
        uint4 v0 = base[s0 * 16 + cl];
        uint4 v1 = base[s1 * 16 + cl];
        const uint4* vv[2] = {&v0, &v1};
#pragma unroll
        for (int q = 0; q < 2; q++) {
            const __half2* hp = (const __half2*)vv[q];
#pragma unroll
            for (int j = 0; j < 4; j++) {
                float2 f = __half22float2(hp[j]);
                acc[2 * j] += f.x; acc[2 * j + 1] += f.y;
            }
        }
        e += 4;
    }
    for (; e < end; e += 2) {
        uint4 v = base[g_csr[e] * 16 + cl];
        const __half2* hp = (const __half2*)&v;
#pragma unroll
        for (int j = 0; j < 4; j++) {
            float2 f = __half22float2(hp[j]);
            acc[2 * j] += f.x; acc[2 * j + 1] += f.y;
        }
    }
#pragma unroll
    for (int j = 0; j < 8; j++)
        acc[j] += __shfl_xor_sync(0xffffffffu, acc[j], 16);
    if (h == 0) {
        uint4 r;
        ((__half2*)&r)[0] = __floats2half2_rn(acc[0], acc[1]);
        ((__half2*)&r)[1] = __floats2half2_rn(acc[2], acc[3]);
        ((__half2*)&r)[2] = __floats2half2_rn(acc[4], acc[5]);
        ((__half2*)&r)[3] = __floats2half2_rn(acc[6], acc[7]);
        ((uint4*)o)[gw * 16 + cl] = r;
    }
}

// ---------------- launch ----------------
extern "C" void kernel_launch(void* const* d_in, const int* in_sizes, int n_in,
                              void* d_out, int out_size) {
    const float* x    = (const float*)d_in[0];
    const void*  ei   = d_in[1];
    const float* W1   = (const float*)d_in[2];
    const float* b1   = (const float*)d_in[3];
    const float* W2   = (const float*)d_in[4];
    const float* b2   = (const float*)d_in[5];
    const float* Wout = (const float*)d_in[6];
    const float* bout = (const float*)d_in[7];
    float* out = (float*)d_out;

    __half *hA, *hB, *w1h, *w1l, *w2h, *w2l, *woh, *wol;
    float *bw1, *bw2;
    cudaGetSymbolAddress((void**)&hA, g_hA);
    cudaGetSymbolAddress((void**)&hB, g_hB);
    cudaGetSymbolAddress((void**)&w1h, g_w1h); cudaGetSymbolAddress((void**)&w1l, g_w1l);
    cudaGetSymbolAddress((void**)&w2h, g_w2h); cudaGetSymbolAddress((void**)&w2l, g_w2l);
    cudaGetSymbolAddress((void**)&woh, g_woh); cudaGetSymbolAddress((void**)&wol, g_wol);
    cudaGetSymbolAddress((void**)&bw1, g_bw1); cudaGetSymbolAddress((void**)&bw2, g_bw2);

    const int SM128 = 32768 + 2 * 128 * 256;  // 98304
    static cudaStream_t s2 = nullptr, s3 = nullptr;
    static cudaEvent_t evF = nullptr, evZ = nullptr, evH = nullptr,
                       evO = nullptr, evFl = nullptr, evJ = nullptr, evJ2 = nullptr;
    if (!s2) {
        cudaFuncSetAttribute((const void*)gemm_on<128, 1, 0>, cudaFuncAttributeMaxDynamicSharedMemorySize, SM128);
        cudaFuncSetAttribute((const void*)gemm_fused_out, cudaFuncAttributeMaxDynamicSharedMemorySize, SM128);
        cudaStreamCreateWithFlags(&s2, cudaStreamNonBlocking);
        cudaStreamCreateWithFlags(&s3, cudaStreamNonBlocking);
        cudaEventCreateWithFlags(&evF, cudaEventDisableTiming);
        cudaEventCreateWithFlags(&evZ, cudaEventDisableTiming);
        cudaEventCreateWithFlags(&evH, cudaEventDisableTiming);
        cudaEventCreateWithFlags(&evO, cudaEventDisableTiming);
        cudaEventCreateWithFlags(&evFl, cudaEventDisableTiming);
        cudaEventCreateWithFlags(&evJ, cudaEventDisableTiming);
        cudaEventCreateWithFlags(&evJ2, cudaEventDisableTiming);
    }

    const int gx = (NN + 127) / 128;         // 391
    const int gg = (NN * 32 + 255) / 256;    // 6250
    const int HALF = EE / 2;
    const int geh = (HALF + 1023) / 1024;    // 293

    // fork: CSR build on two side streams
    cudaEventRecord(evF, 0);
    cudaStreamWaitEvent(s2, evF, 0);
    zero_detect_kernel<<<NB, 256, 0, s2>>>((const unsigned int*)ei);
    cudaEventRecord(evZ, s2);
    cudaStreamWaitEvent(s3, evZ, 0);
    hist_half<<<geh, 256, 0, s2>>>(ei, 0, HALF);
    hist_half<<<geh, 256, 0, s3>>>(ei, HALF, EE);
    cudaEventRecord(evH, s3);
    cudaStreamWaitEvent(s2, evH, 0);
    partial_kernel<<<NB, 256, 0, s2>>>();
    offs_kernel<<<NB, 256, 0, s2>>>();
    cudaEventRecord(evO, s2);
    cudaStreamWaitEvent(s3, evO, 0);
    fill_half<<<geh, 256, 0, s2>>>(ei, 0, HALF);
    fill_half<<<geh, 256, 0, s3>>>(ei, HALF, EE);
    cudaEventRecord(evFl, s3);
    cudaStreamWaitEvent(s2, evFl, 0);
    cudaEventRecord(evJ, s2);          // gathers need off+csr
    adeg_kernel<<<NB, 256, 0, s2>>>();
    cudaEventRecord(evJ2, s2);         // rowbias gemms need adeg/degf

    // main stream: prep (W1^2, W2^2, Wout, bw) + convert x (CSR-independent)
    const int PREP = 32768 + DOUT * DD + 2 * DD;
    prep_all_kernel<<<(PREP + 255) / 256, 256>>>(W1, W2, Wout, b1, b2);
    conv_x_kernel<<<(NN * DD / 4 + 255) / 256, 256>>>(x);   // hA = fp16(x)

    cudaStreamWaitEvent(0, evJ, 0);    // CSR ready

    // layer 1: relu(A^2(x)W1^2 + adeg*(b1W1) + deg*b1)
    gather_kernel<<<gg, 256>>>(hA, hB);        // hB = A x
    gather_kernel<<<gg, 256>>>(hB, hA);        // hA = A^2 x
    cudaStreamWaitEvent(0, evJ2, 0);           // adeg/degf ready
    gemm_on<128, 1, 0><<<gx, 256, SM128>>>(hA, w1h, w1l, b1, bw1, hB);
    // layer 2 + output projection (fused)
    gather_kernel<<<gg, 256>>>(hB, hA);        // hA = A h1
    gather_kernel<<<gg, 256>>>(hA, hB);        // hB = A^2 h1
    gemm_fused_out<<<gx, 256, SM128>>>(hB, w2h, w2l, b2, bw2, woh, wol, bout, out);
}